// round 1
// baseline (speedup 1.0000x reference)
#include <cuda_runtime.h>
#include <cstddef>

// ---------------- problem constants ----------------
#define BATCH  32
#define SEQ    197
#define BD     768
#define NH     12
#define DH     64
#define NLAY   12
#define FF     3072
#define NCLS   1000
#define NTOK   (BATCH * SEQ)     // 6304
#define NPATCH (BATCH * 196)     // 6272
#define SPAD   224               // padded seq for attention tiles

// ---------------- device scratch (bss, no allocation) ----------------
__device__ __align__(128) float g_x[(size_t)NTOK * BD];
__device__ __align__(128) float g_h[(size_t)NTOK * BD];
__device__ __align__(128) float g_q[(size_t)NTOK * BD];
__device__ __align__(128) float g_k[(size_t)NTOK * BD];
__device__ __align__(128) float g_v[(size_t)NTOK * BD];
__device__ __align__(128) float g_attn[(size_t)NTOK * BD];
__device__ __align__(128) float g_ff[(size_t)NTOK * FF];
__device__ __align__(128) float g_col[(size_t)NPATCH * BD];
__device__ __align__(128) float g_wT[(size_t)BD * BD];
__device__ __align__(128) float g_cls[(size_t)BATCH * BD];

// ---------------- generic tiled fp32 GEMM ----------------
// C[m,n] = epi( sum_k A[m,k]*B[k,n] + bias[n] ), epi: optional GELU, optional +res
// Requires N % 64 == 0, K % 16 == 0 (true for every call here). M guarded.
#define TBM 64
#define TBN 64
#define TBK 16

__global__ __launch_bounds__(256) void gemm_kernel(
    const float* __restrict__ A, const float* __restrict__ B,
    const float* __restrict__ bias, const float* __restrict__ res,
    float* __restrict__ C, int M, int N, int K, int act)
{
    __shared__ __align__(16) float As[TBK][TBM + 4];   // transposed, padded (row = 272B, 16B-mult)
    __shared__ __align__(16) float Bs[TBK][TBN];

    const int tid = threadIdx.x;
    const int block_m = blockIdx.y * TBM;
    const int block_n = blockIdx.x * TBN;

    const int a_row  = tid >> 2;          // 0..63
    const int a_col4 = (tid & 3) * 4;     // 0,4,8,12
    const int b_row  = tid >> 4;          // 0..15
    const int b_col4 = (tid & 15) * 4;    // 0..60

    const int ty = tid >> 4;              // 0..15 -> m micro
    const int tx = tid & 15;              // 0..15 -> n micro

    float acc[4][4];
#pragma unroll
    for (int i = 0; i < 4; i++)
#pragma unroll
        for (int j = 0; j < 4; j++) acc[i][j] = 0.f;

    const int gArow = block_m + a_row;
    const bool a_valid = (gArow < M);

    for (int k0 = 0; k0 < K; k0 += TBK) {
        float4 av = a_valid ? *(const float4*)(A + (size_t)gArow * K + k0 + a_col4)
                            : make_float4(0.f, 0.f, 0.f, 0.f);
        As[a_col4 + 0][a_row] = av.x;
        As[a_col4 + 1][a_row] = av.y;
        As[a_col4 + 2][a_row] = av.z;
        As[a_col4 + 3][a_row] = av.w;

        float4 bv = *(const float4*)(B + (size_t)(k0 + b_row) * N + block_n + b_col4);
        *(float4*)&Bs[b_row][b_col4] = bv;

        __syncthreads();

#pragma unroll
        for (int k = 0; k < TBK; k++) {
            float4 a4 = *(const float4*)&As[k][ty * 4];
            float4 b4 = *(const float4*)&Bs[k][tx * 4];
            float ar[4] = {a4.x, a4.y, a4.z, a4.w};
            float br[4] = {b4.x, b4.y, b4.z, b4.w};
#pragma unroll
            for (int i = 0; i < 4; i++)
#pragma unroll
                for (int j = 0; j < 4; j++)
                    acc[i][j] += ar[i] * br[j];
        }
        __syncthreads();
    }

#pragma unroll
    for (int i = 0; i < 4; i++) {
        int m = block_m + ty * 4 + i;
        if (m >= M) continue;
#pragma unroll
        for (int j = 0; j < 4; j++) {
            int n = block_n + tx * 4 + j;
            float v = acc[i][j];
            if (bias) v += bias[n];
            if (act == 1) v = 0.5f * v * (1.f + erff(v * 0.70710678118654752440f));
            if (res) v += res[(size_t)m * N + n];
            C[(size_t)m * N + n] = v;
        }
    }
}

// ---------------- layernorm (block per row) ----------------
__device__ __forceinline__ float block_sum(float v, float* red)
{
#pragma unroll
    for (int o = 16; o; o >>= 1) v += __shfl_xor_sync(0xffffffffu, v, o);
    int w = threadIdx.x >> 5;
    if ((threadIdx.x & 31) == 0) red[w] = v;
    __syncthreads();
    float t = 0.f;
    if (threadIdx.x < 32) {
        t = (threadIdx.x < 8) ? red[threadIdx.x] : 0.f;
#pragma unroll
        for (int o = 4; o; o >>= 1) t += __shfl_xor_sync(0xffffffffu, t, o);
        if (threadIdx.x == 0) red[0] = t;
    }
    __syncthreads();
    float r = red[0];
    __syncthreads();
    return r;
}

__global__ __launch_bounds__(256) void ln_kernel(
    const float* __restrict__ X, const float* __restrict__ g,
    const float* __restrict__ bb, float* __restrict__ out, size_t in_stride)
{
    __shared__ float red[8];
    const int tid = threadIdx.x;
    const float* xr = X + (size_t)blockIdx.x * in_stride;
    float v0 = xr[tid], v1 = xr[tid + 256], v2 = xr[tid + 512];
    float s = block_sum(v0 + v1 + v2, red);
    float mean = s * (1.f / 768.f);
    float d0 = v0 - mean, d1 = v1 - mean, d2 = v2 - mean;
    float sq = block_sum(d0 * d0 + d1 * d1 + d2 * d2, red);
    float rstd = rsqrtf(sq * (1.f / 768.f) + 1e-5f);
    float* orow = out + (size_t)blockIdx.x * BD;
    orow[tid]       = d0 * rstd * g[tid]       + bb[tid];
    orow[tid + 256] = d1 * rstd * g[tid + 256] + bb[tid + 256];
    orow[tid + 512] = d2 * rstd * g[tid + 512] + bb[tid + 512];
}

// ---------------- attention: one block per (b, h) ----------------
// dyn smem: Ks[SPAD*65] + Vs[SPAD*65] + Ps[8*SPAD]
#define ATTN_SMEM_FLOATS (SPAD * 65 * 2 + 8 * SPAD)
#define ATTN_SMEM_BYTES  (ATTN_SMEM_FLOATS * 4)

__global__ __launch_bounds__(256) void attn_kernel(
    const float* __restrict__ Q, const float* __restrict__ K,
    const float* __restrict__ V, float* __restrict__ O)
{
    extern __shared__ float sm[];
    float* Ks = sm;
    float* Vs = Ks + SPAD * 65;
    float* Ps = Vs + SPAD * 65;

    const int bh = blockIdx.x;
    const int b = bh / NH, h = bh % NH;
    const size_t base = (size_t)b * SEQ * BD + (size_t)h * DH;
    const int tid = threadIdx.x;

    for (int i = tid; i < SPAD * 65; i += 256) {
        int s = i / 65, d = i - s * 65;
        float kv = 0.f, vv = 0.f;
        if (s < SEQ && d < DH) {
            kv = K[base + (size_t)s * BD + d];
            vv = V[base + (size_t)s * BD + d];
        }
        Ks[i] = kv;
        Vs[i] = vv;
    }
    __syncthreads();

    const int warp = tid >> 5, lane = tid & 31;
    float* Pw = Ps + warp * SPAD;

    for (int s = warp; s < SEQ; s += 8) {
        const float* q = Q + base + (size_t)s * BD;
        float acc[7];
#pragma unroll
        for (int j = 0; j < 7; j++) acc[j] = 0.f;

#pragma unroll 8
        for (int d = 0; d < DH; d++) {
            float qd = __ldg(q + d);
#pragma unroll
            for (int j = 0; j < 7; j++) {
                int t = lane + j * 32;     // < SPAD, zero-padded rows beyond SEQ
                acc[j] += qd * Ks[t * 65 + d];
            }
        }
#pragma unroll
        for (int j = 0; j < 7; j++) acc[j] *= 0.125f;   // 1/sqrt(64)

        // softmax over t
        float mx = -1e30f;
#pragma unroll
        for (int j = 0; j < 7; j++)
            if (lane + j * 32 < SEQ) mx = fmaxf(mx, acc[j]);
#pragma unroll
        for (int o = 16; o; o >>= 1) mx = fmaxf(mx, __shfl_xor_sync(0xffffffffu, mx, o));

        float sum = 0.f;
        float ex[7];
#pragma unroll
        for (int j = 0; j < 7; j++) {
            int t = lane + j * 32;
            float e = (t < SEQ) ? __expf(acc[j] - mx) : 0.f;
            ex[j] = e;
            sum += e;
        }
#pragma unroll
        for (int o = 16; o; o >>= 1) sum += __shfl_xor_sync(0xffffffffu, sum, o);
        float inv = 1.f / sum;

#pragma unroll
        for (int j = 0; j < 7; j++) {
            int t = lane + j * 32;
            if (t < SEQ) Pw[t] = ex[j] * inv;
        }
        __syncwarp();

        float o0 = 0.f, o1 = 0.f;
        for (int t = 0; t < SEQ; t++) {
            float p = Pw[t];
            o0 += p * Vs[t * 65 + lane];
            o1 += p * Vs[t * 65 + lane + 32];
        }
        O[base + (size_t)s * BD + lane]      = o0;
        O[base + (size_t)s * BD + lane + 32] = o1;
        __syncwarp();
    }
}

// ---------------- small kernels ----------------
__global__ void transpose_k(const float* __restrict__ src, float* __restrict__ dst)
{
    int idx = blockIdx.x * blockDim.x + threadIdx.x;
    if (idx < BD * BD) {
        int d = idx / BD, k = idx - d * BD;
        dst[(size_t)k * BD + d] = src[idx];
    }
}

__global__ void im2col_k(const float* __restrict__ X, float* __restrict__ col)
{
    int idx = blockIdx.x * blockDim.x + threadIdx.x;
    if (idx >= NPATCH * BD) return;
    int m = idx / BD, kk = idx - m * BD;
    int b = m / 196, hw = m - b * 196;
    int ph = hw / 14, pw = hw - ph * 14;
    int c = kk >> 8, r = kk & 255, p = r >> 4, q = r & 15;
    col[idx] = X[((size_t)(b * 3 + c) * 224 + ph * 16 + p) * 224 + pw * 16 + q];
}

__global__ void assemble_k(const float* __restrict__ patches, const float* __restrict__ cls,
                           const float* __restrict__ pos, float* __restrict__ x)
{
    int idx = blockIdx.x * blockDim.x + threadIdx.x;
    if (idx >= NTOK * BD) return;
    int d = idx % BD;
    int t = idx / BD;
    int b = t / SEQ, s = t - b * SEQ;
    float v = (s == 0) ? cls[d] : patches[((size_t)b * 196 + (s - 1)) * BD + d];
    x[idx] = v + pos[(size_t)s * BD + d];
}

__global__ __launch_bounds__(256) void head_kernel(
    const float* __restrict__ xc, const float* __restrict__ W,
    const float* __restrict__ bias, float* __restrict__ out)
{
    __shared__ float xs[BD];
    const int b = blockIdx.x;
    for (int i = threadIdx.x; i < BD; i += 256) xs[i] = xc[(size_t)b * BD + i];
    __syncthreads();

    const int n0 = threadIdx.x;
    float acc[4] = {0.f, 0.f, 0.f, 0.f};
    for (int k = 0; k < BD; k++) {
        float xv = xs[k];
#pragma unroll
        for (int j = 0; j < 4; j++) {
            int n = n0 + j * 256;
            if (n < NCLS) acc[j] += xv * W[(size_t)k * NCLS + n];
        }
    }
#pragma unroll
    for (int j = 0; j < 4; j++) {
        int n = n0 + j * 256;
        if (n < NCLS) out[(size_t)b * NCLS + n] = acc[j] + bias[n];
    }
}

// ---------------- launch ----------------
extern "C" void kernel_launch(void* const* d_in, const int* in_sizes, int n_in,
                              void* d_out, int out_size)
{
    const float* X       = (const float*)d_in[0];
    const float* patch_w = (const float*)d_in[1];
    const float* patch_b = (const float*)d_in[2];
    const float* cls_tok = (const float*)d_in[3];
    const float* pos_emb = (const float*)d_in[4];
    const float* ln1_g   = (const float*)d_in[5];
    const float* ln1_b   = (const float*)d_in[6];
    const float* Wq      = (const float*)d_in[7];
    const float* bq      = (const float*)d_in[8];
    const float* Wk      = (const float*)d_in[9];
    const float* bk      = (const float*)d_in[10];
    const float* Wv      = (const float*)d_in[11];
    const float* bv      = (const float*)d_in[12];
    const float* Wo      = (const float*)d_in[13];
    const float* bo      = (const float*)d_in[14];
    const float* ln2_g   = (const float*)d_in[15];
    const float* ln2_b   = (const float*)d_in[16];
    const float* Wf1     = (const float*)d_in[17];
    const float* bf1     = (const float*)d_in[18];
    const float* Wf2     = (const float*)d_in[19];
    const float* bf2     = (const float*)d_in[20];
    const float* lnf_g   = (const float*)d_in[21];
    const float* lnf_b   = (const float*)d_in[22];
    const float* head_w  = (const float*)d_in[23];
    const float* head_b  = (const float*)d_in[24];
    float* out = (float*)d_out;

    float *x, *h, *q, *k, *v, *attn, *ff, *col, *wT, *cls;
    cudaGetSymbolAddress((void**)&x,    g_x);
    cudaGetSymbolAddress((void**)&h,    g_h);
    cudaGetSymbolAddress((void**)&q,    g_q);
    cudaGetSymbolAddress((void**)&k,    g_k);
    cudaGetSymbolAddress((void**)&v,    g_v);
    cudaGetSymbolAddress((void**)&attn, g_attn);
    cudaGetSymbolAddress((void**)&ff,   g_ff);
    cudaGetSymbolAddress((void**)&col,  g_col);
    cudaGetSymbolAddress((void**)&wT,   g_wT);
    cudaGetSymbolAddress((void**)&cls,  g_cls);

    cudaFuncSetAttribute(attn_kernel, cudaFuncAttributeMaxDynamicSharedMemorySize,
                         ATTN_SMEM_BYTES);

    const dim3 gD(BD / TBN, (NTOK + TBM - 1) / TBM);        // N=768
    const dim3 gF1(FF / TBN, (NTOK + TBM - 1) / TBM);       // N=3072
    const dim3 gPatch(BD / TBN, (NPATCH + TBM - 1) / TBM);  // 6272 rows

    // ---- patch embed ----
    transpose_k<<<(BD * BD + 255) / 256, 256>>>(patch_w, wT);
    im2col_k<<<(NPATCH * BD + 255) / 256, 256>>>(X, col);
    gemm_kernel<<<gPatch, 256>>>(col, wT, patch_b, nullptr, h, NPATCH, BD, BD, 0);
    assemble_k<<<(NTOK * BD + 255) / 256, 256>>>(h, cls_tok, pos_emb, x);

    // ---- transformer blocks ----
    for (int l = 0; l < NLAY; l++) {
        const size_t wo_off = (size_t)l * BD * BD;
        const size_t f1_off = (size_t)l * BD * FF;
        const size_t f2_off = (size_t)l * FF * BD;

        ln_kernel<<<NTOK, 256>>>(x, ln1_g + l * BD, ln1_b + l * BD, h, BD);

        gemm_kernel<<<gD, 256>>>(h, Wq + wo_off, bq + l * BD, nullptr, q, NTOK, BD, BD, 0);
        gemm_kernel<<<gD, 256>>>(h, Wk + wo_off, bk + l * BD, nullptr, k, NTOK, BD, BD, 0);
        gemm_kernel<<<gD, 256>>>(h, Wv + wo_off, bv + l * BD, nullptr, v, NTOK, BD, BD, 0);

        attn_kernel<<<BATCH * NH, 256, ATTN_SMEM_BYTES>>>(q, k, v, attn);

        gemm_kernel<<<gD, 256>>>(attn, Wo + wo_off, bo + l * BD, x, x, NTOK, BD, BD, 0);

        ln_kernel<<<NTOK, 256>>>(x, ln2_g + l * BD, ln2_b + l * BD, h, BD);

        gemm_kernel<<<gF1, 256>>>(h, Wf1 + f1_off, bf1 + l * FF, nullptr, ff, NTOK, FF, BD, 1);
        gemm_kernel<<<gD, 256>>>(ff, Wf2 + f2_off, bf2 + l * BD, x, x, NTOK, BD, FF, 0);
    }

    // ---- final LN on cls rows + head ----
    ln_kernel<<<BATCH, 256>>>(x, lnf_g, lnf_b, cls, (size_t)SEQ * BD);
    head_kernel<<<BATCH, 256>>>(cls, head_w, head_b, out);
}

// round 5
// speedup vs baseline: 2.3349x; 2.3349x over previous
#include <cuda_runtime.h>
#include <cuda_bf16.h>
#include <cstdint>
#include <cstddef>

// ---------------- problem constants ----------------
#define BATCH  32
#define SEQ    197
#define BD     768
#define NH     12
#define DH     64
#define NLAY   12
#define FF     3072
#define NCLS   1000
#define NTOK   (BATCH * SEQ)     // 6304
#define NPATCH (BATCH * 196)     // 6272
#define SPAD   224

#define SZ_D2  (768 * 768)
#define SZ_DF  (768 * 3072)
#define LW     ((size_t)(4 * SZ_D2) + (size_t)(2 * SZ_DF))
#define OFF_Q  ((size_t)0)
#define OFF_K  ((size_t)SZ_D2)
#define OFF_V  ((size_t)(2 * SZ_D2))
#define OFF_O  ((size_t)(3 * SZ_D2))
#define OFF_F1 ((size_t)(4 * SZ_D2))
#define OFF_F2 ((size_t)(4 * SZ_D2) + (size_t)SZ_DF)

// ---------------- device scratch (bss, no allocation) ----------------
__device__ __align__(128) float g_x[(size_t)NTOK * BD];
__device__ __align__(128) float g_h[(size_t)NTOK * BD];
__device__ __align__(128) float g_q[(size_t)NTOK * BD];
__device__ __align__(128) float g_k[(size_t)NTOK * BD];
__device__ __align__(128) float g_v[(size_t)NTOK * BD];
__device__ __align__(128) float g_cls[(size_t)BATCH * BD];

__device__ __align__(128) __nv_bfloat16 g_hh[(size_t)NTOK * BD];
__device__ __align__(128) __nv_bfloat16 g_hl[(size_t)NTOK * BD];
__device__ __align__(128) __nv_bfloat16 g_ah[(size_t)NTOK * BD];
__device__ __align__(128) __nv_bfloat16 g_al[(size_t)NTOK * BD];
__device__ __align__(128) __nv_bfloat16 g_fh[(size_t)NTOK * FF];
__device__ __align__(128) __nv_bfloat16 g_fl[(size_t)NTOK * FF];
__device__ __align__(128) __nv_bfloat16 g_ch[(size_t)NPATCH * BD];
__device__ __align__(128) __nv_bfloat16 g_cl[(size_t)NPATCH * BD];
__device__ __align__(128) __nv_bfloat16 g_wh[(size_t)NLAY * LW];
__device__ __align__(128) __nv_bfloat16 g_wl[(size_t)NLAY * LW];
__device__ __align__(128) __nv_bfloat16 g_pwh[(size_t)SZ_D2];
__device__ __align__(128) __nv_bfloat16 g_pwl[(size_t)SZ_D2];

// ---------------- PTX helpers (generic compute_103-safe) ----------------
__device__ __forceinline__ uint32_t smem_u32(const void* p) {
    uint32_t a;
    asm("{ .reg .u64 t; cvta.to.shared.u64 t, %1; cvt.u32.u64 %0, t; }" : "=r"(a) : "l"(p));
    return a;
}

__device__ __forceinline__ void cp16(uint32_t dst, const void* src) {
    asm volatile("cp.async.cg.shared.global [%0], [%1], 16;" :: "r"(dst), "l"(src) : "memory");
}
#define CP_COMMIT() asm volatile("cp.async.commit_group;" ::: "memory")
#define CP_WAIT1()  asm volatile("cp.async.wait_group 1;" ::: "memory")
#define CP_WAIT0()  asm volatile("cp.async.wait_group 0;" ::: "memory")

__device__ __forceinline__ void ldsm4(uint32_t* r, uint32_t addr) {
    asm volatile("ldmatrix.sync.aligned.m8n8.x4.shared.b16 {%0,%1,%2,%3}, [%4];"
        : "=r"(r[0]), "=r"(r[1]), "=r"(r[2]), "=r"(r[3]) : "r"(addr));
}

__device__ __forceinline__ void mma_bf16(float* d, const uint32_t* a, const uint32_t* b) {
    asm volatile(
        "mma.sync.aligned.m16n8k16.row.col.f32.bf16.bf16.f32 "
        "{%0,%1,%2,%3}, {%4,%5,%6,%7}, {%8,%9}, {%0,%1,%2,%3};"
        : "+f"(d[0]), "+f"(d[1]), "+f"(d[2]), "+f"(d[3])
        : "r"(a[0]), "r"(a[1]), "r"(a[2]), "r"(a[3]), "r"(b[0]), "r"(b[1]));
}

// ---------------- tensor-core split-bf16 GEMM ----------------
// D[m,n] = sum_k A[m,k] * B[n,k]   (A, B given as hi/lo bf16 splits, both K-major)
// 3-pass split precision: Ahi*Bhi + Ahi*Blo + Alo*Bhi
// mode 0: Cf = D + bias
// mode 1: gelu(D + bias) -> (Chi, Clo) split bf16
// mode 2: Cf = D + bias + res
#define TILE_B  10240                // 128 rows * 80B (32 bf16 + 8 pad)
#define STAGE_B (4 * TILE_B)         // Ah, Al, Bh, Bl
#define GT_SMEM (2 * STAGE_B)        // 81920 double buffered

__global__ __launch_bounds__(256, 2) void gemm_tc(
    const __nv_bfloat16* __restrict__ Ahi, const __nv_bfloat16* __restrict__ Alo,
    const __nv_bfloat16* __restrict__ Bhi, const __nv_bfloat16* __restrict__ Blo,
    const float* __restrict__ bias, const float* __restrict__ res,
    float* __restrict__ Cf, __nv_bfloat16* __restrict__ Chi, __nv_bfloat16* __restrict__ Clo,
    int M, int N, int K, int mode)
{
    extern __shared__ __align__(128) char smem[];
    const uint32_t sb = smem_u32(smem);
    const int tid = threadIdx.x, wid = tid >> 5, lane = tid & 31;
    const int bm = blockIdx.y * 128, bn = blockIdx.x * 128;
    const int wm = (wid & 1) * 64, wn = (wid >> 1) * 32;

    float acc[4][4][4];
#pragma unroll
    for (int mt = 0; mt < 4; mt++)
#pragma unroll
        for (int nt = 0; nt < 4; nt++)
#pragma unroll
            for (int e = 0; e < 4; e++) acc[mt][nt][e] = 0.f;

    const __nv_bfloat16* src[4] = {Ahi, Alo, Bhi, Blo};
    const int NKs = K >> 5;

    auto load_stage = [&](int st, int k0) {
        uint32_t base = sb + (uint32_t)st * STAGE_B;
#pragma unroll
        for (int t = 0; t < 4; t++) {
#pragma unroll
            for (int j = 0; j < 2; j++) {
                int cid = tid + (j << 8);
                int row = cid >> 2, chk = cid & 3;
                int rg = (t < 2) ? min(bm + row, M - 1) : (bn + row);
                cp16(base + (uint32_t)(t * TILE_B + row * 80 + chk * 16),
                     src[t] + (size_t)rg * K + k0 + chk * 8);
            }
        }
        CP_COMMIT();
    };

    load_stage(0, 0);
    for (int i = 0; i < NKs; i++) {
        if (i + 1 < NKs) { load_stage((i + 1) & 1, (i + 1) << 5); CP_WAIT1(); }
        else            { CP_WAIT0(); }
        __syncthreads();

        const uint32_t stb = sb + (uint32_t)(i & 1) * STAGE_B;
        const int g = lane >> 3, r = lane & 7;

#pragma unroll
        for (int pass = 0; pass < 3; pass++) {
            const uint32_t Abase = stb + (pass == 2 ? TILE_B : 0);
            const uint32_t Bbase = stb + 2 * TILE_B + (pass == 1 ? TILE_B : 0);
#pragma unroll
            for (int k16 = 0; k16 < 2; k16++) {
                uint32_t bfr[4][2];
#pragma unroll
                for (int nt2 = 0; nt2 < 2; nt2++) {
                    uint32_t b4[4];
                    int nloc = wn + nt2 * 16 + (g >> 1) * 8 + r;
                    int kk = k16 * 16 + (g & 1) * 8;
                    ldsm4(b4, Bbase + (uint32_t)(nloc * 80 + kk * 2));
                    bfr[nt2 * 2 + 0][0] = b4[0]; bfr[nt2 * 2 + 0][1] = b4[1];
                    bfr[nt2 * 2 + 1][0] = b4[2]; bfr[nt2 * 2 + 1][1] = b4[3];
                }
#pragma unroll
                for (int mt = 0; mt < 4; mt++) {
                    uint32_t a4[4];
                    int mloc = wm + mt * 16 + (g & 1) * 8 + r;
                    int kk = k16 * 16 + (g >> 1) * 8;
                    ldsm4(a4, Abase + (uint32_t)(mloc * 80 + kk * 2));
#pragma unroll
                    for (int nt = 0; nt < 4; nt++)
                        mma_bf16(acc[mt][nt], a4, bfr[nt]);
                }
            }
        }
        __syncthreads();
    }

    // ---- epilogue: register-direct, fragment layout ----
    const int r0 = lane >> 2, c0 = (lane & 3) * 2;
    float bv[4][2];
#pragma unroll
    for (int nt = 0; nt < 4; nt++) {
        int n = bn + wn + nt * 8 + c0;
        bv[nt][0] = __ldg(bias + n);
        bv[nt][1] = __ldg(bias + n + 1);
    }

#pragma unroll
    for (int mt = 0; mt < 4; mt++) {
#pragma unroll
        for (int half = 0; half < 2; half++) {
            int m = bm + wm + mt * 16 + half * 8 + r0;
            if (m >= M) continue;
#pragma unroll
            for (int nt = 0; nt < 4; nt++) {
                int n = bn + wn + nt * 8 + c0;
                float v0 = acc[mt][nt][half * 2 + 0] + bv[nt][0];
                float v1 = acc[mt][nt][half * 2 + 1] + bv[nt][1];
                if (mode == 1) {
                    v0 = 0.5f * v0 * (1.f + erff(v0 * 0.70710678118654752440f));
                    v1 = 0.5f * v1 * (1.f + erff(v1 * 0.70710678118654752440f));
                    __nv_bfloat16 h0 = __float2bfloat16(v0);
                    __nv_bfloat16 h1 = __float2bfloat16(v1);
                    __nv_bfloat162 hi; hi.x = h0; hi.y = h1;
                    __nv_bfloat162 lo;
                    lo.x = __float2bfloat16(v0 - __bfloat162float(h0));
                    lo.y = __float2bfloat16(v1 - __bfloat162float(h1));
                    *(__nv_bfloat162*)(Chi + (size_t)m * N + n) = hi;
                    *(__nv_bfloat162*)(Clo + (size_t)m * N + n) = lo;
                } else {
                    if (mode == 2) {
                        float2 rr = *(const float2*)(res + (size_t)m * N + n);
                        v0 += rr.x; v1 += rr.y;
                    }
                    float2 o; o.x = v0; o.y = v1;
                    *(float2*)(Cf + (size_t)m * N + n) = o;
                }
            }
        }
    }
}

// ---------------- weight transpose + split: W[K,N] fp32 -> (hi,lo)[N,K] bf16 ----------------
__global__ __launch_bounds__(256) void wsplit_T(
    const float* __restrict__ src, __nv_bfloat16* __restrict__ dh, __nv_bfloat16* __restrict__ dl,
    int K, int N, size_t ls_in, size_t ls_out)
{
    __shared__ float t[32][33];
    const int l = blockIdx.z;
    const int kb = blockIdx.y << 5, nb = blockIdx.x << 5;
    const int tx = threadIdx.x & 31, ty = threadIdx.x >> 5;
    const float* s = src + (size_t)l * ls_in;
#pragma unroll
    for (int r = 0; r < 4; r++) {
        int row = ty + (r << 3);
        t[row][tx] = s[(size_t)(kb + row) * N + nb + tx];
    }
    __syncthreads();
    __nv_bfloat16* oh = dh + (size_t)l * ls_out;
    __nv_bfloat16* ol = dl + (size_t)l * ls_out;
#pragma unroll
    for (int r = 0; r < 4; r++) {
        int row = ty + (r << 3);
        float v = t[tx][row];
        __nv_bfloat16 h = __float2bfloat16(v);
        size_t o = (size_t)(nb + row) * K + kb + tx;
        oh[o] = h;
        ol[o] = __float2bfloat16(v - __bfloat162float(h));
    }
}

__global__ void split_ew(const float* __restrict__ s, __nv_bfloat16* __restrict__ dh,
                         __nv_bfloat16* __restrict__ dl, int n)
{
    int i = blockIdx.x * blockDim.x + threadIdx.x;
    if (i < n) {
        float v = s[i];
        __nv_bfloat16 h = __float2bfloat16(v);
        dh[i] = h;
        dl[i] = __float2bfloat16(v - __bfloat162float(h));
    }
}

// ---------------- layernorm ----------------
__device__ __forceinline__ float block_sum(float v, float* red)
{
#pragma unroll
    for (int o = 16; o; o >>= 1) v += __shfl_xor_sync(0xffffffffu, v, o);
    int w = threadIdx.x >> 5;
    if ((threadIdx.x & 31) == 0) red[w] = v;
    __syncthreads();
    float t = 0.f;
    if (threadIdx.x < 32) {
        t = (threadIdx.x < 8) ? red[threadIdx.x] : 0.f;
#pragma unroll
        for (int o = 4; o; o >>= 1) t += __shfl_xor_sync(0xffffffffu, t, o);
        if (threadIdx.x == 0) red[0] = t;
    }
    __syncthreads();
    float r = red[0];
    __syncthreads();
    return r;
}

__global__ __launch_bounds__(256) void ln_kernel(
    const float* __restrict__ X, const float* __restrict__ g,
    const float* __restrict__ bb, float* __restrict__ out, size_t in_stride)
{
    __shared__ float red[8];
    const int tid = threadIdx.x;
    const float* xr = X + (size_t)blockIdx.x * in_stride;
    float v0 = xr[tid], v1 = xr[tid + 256], v2 = xr[tid + 512];
    float s = block_sum(v0 + v1 + v2, red);
    float mean = s * (1.f / 768.f);
    float d0 = v0 - mean, d1 = v1 - mean, d2 = v2 - mean;
    float sq = block_sum(d0 * d0 + d1 * d1 + d2 * d2, red);
    float rstd = rsqrtf(sq * (1.f / 768.f) + 1e-5f);
    float* orow = out + (size_t)blockIdx.x * BD;
    orow[tid]       = d0 * rstd * g[tid]       + bb[tid];
    orow[tid + 256] = d1 * rstd * g[tid + 256] + bb[tid + 256];
    orow[tid + 512] = d2 * rstd * g[tid + 512] + bb[tid + 512];
}

__global__ __launch_bounds__(256) void ln_split(
    const float* __restrict__ X, const float* __restrict__ g,
    const float* __restrict__ bb, __nv_bfloat16* __restrict__ oh,
    __nv_bfloat16* __restrict__ ol)
{
    __shared__ float red[8];
    const int tid = threadIdx.x;
    const float* xr = X + (size_t)blockIdx.x * BD;
    float v0 = xr[tid], v1 = xr[tid + 256], v2 = xr[tid + 512];
    float s = block_sum(v0 + v1 + v2, red);
    float mean = s * (1.f / 768.f);
    float d0 = v0 - mean, d1 = v1 - mean, d2 = v2 - mean;
    float sq = block_sum(d0 * d0 + d1 * d1 + d2 * d2, red);
    float rstd = rsqrtf(sq * (1.f / 768.f) + 1e-5f);
    size_t ro = (size_t)blockIdx.x * BD;
#pragma unroll
    for (int j = 0; j < 3; j++) {
        float d = (j == 0) ? d0 : (j == 1) ? d1 : d2;
        int c = tid + j * 256;
        float y = d * rstd * g[c] + bb[c];
        __nv_bfloat16 h = __float2bfloat16(y);
        oh[ro + c] = h;
        ol[ro + c] = __float2bfloat16(y - __bfloat162float(h));
    }
}

// ---------------- attention ----------------
#define ATTN_SMEM_FLOATS (SPAD * 65 * 2 + 8 * SPAD)
#define ATTN_SMEM_BYTES  (ATTN_SMEM_FLOATS * 4)

__global__ __launch_bounds__(256) void attn_kernel(
    const float* __restrict__ Q, const float* __restrict__ K,
    const float* __restrict__ V, __nv_bfloat16* __restrict__ Oh,
    __nv_bfloat16* __restrict__ Ol)
{
    extern __shared__ float sm[];
    float* Ks = sm;
    float* Vs = Ks + SPAD * 65;
    float* Ps = Vs + SPAD * 65;

    const int bh = blockIdx.x;
    const int b = bh / NH, h = bh % NH;
    const size_t base = (size_t)b * SEQ * BD + (size_t)h * DH;
    const int tid = threadIdx.x;

    for (int i = tid; i < SPAD * 65; i += 256) {
        int s = i / 65, d = i - s * 65;
        float kv = 0.f, vv = 0.f;
        if (s < SEQ && d < DH) {
            kv = K[base + (size_t)s * BD + d];
            vv = V[base + (size_t)s * BD + d];
        }
        Ks[i] = kv;
        Vs[i] = vv;
    }
    __syncthreads();

    const int warp = tid >> 5, lane = tid & 31;
    float* Pw = Ps + warp * SPAD;

    for (int s = warp; s < SEQ; s += 8) {
        const float* q = Q + base + (size_t)s * BD;
        float acc[7];
#pragma unroll
        for (int j = 0; j < 7; j++) acc[j] = 0.f;

#pragma unroll 8
        for (int d = 0; d < DH; d++) {
            float qd = __ldg(q + d);
#pragma unroll
            for (int j = 0; j < 7; j++) {
                int t = lane + j * 32;
                acc[j] += qd * Ks[t * 65 + d];
            }
        }
#pragma unroll
        for (int j = 0; j < 7; j++) acc[j] *= 0.125f;

        float mx = -1e30f;
#pragma unroll
        for (int j = 0; j < 7; j++)
            if (lane + j * 32 < SEQ) mx = fmaxf(mx, acc[j]);
#pragma unroll
        for (int o = 16; o; o >>= 1) mx = fmaxf(mx, __shfl_xor_sync(0xffffffffu, mx, o));

        float sum = 0.f;
        float ex[7];
#pragma unroll
        for (int j = 0; j < 7; j++) {
            int t = lane + j * 32;
            float e = (t < SEQ) ? __expf(acc[j] - mx) : 0.f;
            ex[j] = e;
            sum += e;
        }
#pragma unroll
        for (int o = 16; o; o >>= 1) sum += __shfl_xor_sync(0xffffffffu, sum, o);
        float inv = 1.f / sum;

#pragma unroll
        for (int j = 0; j < 7; j++) {
            int t = lane + j * 32;
            if (t < SEQ) Pw[t] = ex[j] * inv;
        }
        __syncwarp();

        float o0 = 0.f, o1 = 0.f;
        for (int t = 0; t < SEQ; t++) {
            float p = Pw[t];
            o0 += p * Vs[t * 65 + lane];
            o1 += p * Vs[t * 65 + lane + 32];
        }
        {
            __nv_bfloat16 h0 = __float2bfloat16(o0);
            Oh[base + (size_t)s * BD + lane] = h0;
            Ol[base + (size_t)s * BD + lane] = __float2bfloat16(o0 - __bfloat162float(h0));
            __nv_bfloat16 h1 = __float2bfloat16(o1);
            Oh[base + (size_t)s * BD + lane + 32] = h1;
            Ol[base + (size_t)s * BD + lane + 32] = __float2bfloat16(o1 - __bfloat162float(h1));
        }
        __syncwarp();
    }
}

// ---------------- small kernels ----------------
__global__ void im2col_split(const float* __restrict__ X, __nv_bfloat16* __restrict__ ch,
                             __nv_bfloat16* __restrict__ cl)
{
    int idx = blockIdx.x * blockDim.x + threadIdx.x;
    if (idx >= NPATCH * BD) return;
    int m = idx / BD, kk = idx - m * BD;
    int b = m / 196, hw = m - b * 196;
    int ph = hw / 14, pw = hw - ph * 14;
    int c = kk >> 8, r = kk & 255, p = r >> 4, q = r & 15;
    float v = X[((size_t)(b * 3 + c) * 224 + ph * 16 + p) * 224 + pw * 16 + q];
    __nv_bfloat16 h = __float2bfloat16(v);
    ch[idx] = h;
    cl[idx] = __float2bfloat16(v - __bfloat162float(h));
}

__global__ void assemble_k(const float* __restrict__ patches, const float* __restrict__ cls,
                           const float* __restrict__ pos, float* __restrict__ x)
{
    int idx = blockIdx.x * blockDim.x + threadIdx.x;
    if (idx >= NTOK * BD) return;
    int d = idx % BD;
    int t = idx / BD;
    int b = t / SEQ, s = t - b * SEQ;
    float v = (s == 0) ? cls[d] : patches[((size_t)b * 196 + (s - 1)) * BD + d];
    x[idx] = v + pos[(size_t)s * BD + d];
}

__global__ __launch_bounds__(256) void head_kernel(
    const float* __restrict__ xc, const float* __restrict__ W,
    const float* __restrict__ bias, float* __restrict__ out)
{
    __shared__ float xs[BD];
    const int b = blockIdx.x;
    for (int i = threadIdx.x; i < BD; i += 256) xs[i] = xc[(size_t)b * BD + i];
    __syncthreads();

    const int n0 = threadIdx.x;
    float acc[4] = {0.f, 0.f, 0.f, 0.f};
    for (int k = 0; k < BD; k++) {
        float xv = xs[k];
#pragma unroll
        for (int j = 0; j < 4; j++) {
            int n = n0 + j * 256;
            if (n < NCLS) acc[j] += xv * W[(size_t)k * NCLS + n];
        }
    }
#pragma unroll
    for (int j = 0; j < 4; j++) {
        int n = n0 + j * 256;
        if (n < NCLS) out[(size_t)b * NCLS + n] = acc[j] + bias[n];
    }
}

// ---------------- launch ----------------
extern "C" void kernel_launch(void* const* d_in, const int* in_sizes, int n_in,
                              void* d_out, int out_size)
{
    const float* X       = (const float*)d_in[0];
    const float* patch_w = (const float*)d_in[1];
    const float* patch_b = (const float*)d_in[2];
    const float* cls_tok = (const float*)d_in[3];
    const float* pos_emb = (const float*)d_in[4];
    const float* ln1_g   = (const float*)d_in[5];
    const float* ln1_b   = (const float*)d_in[6];
    const float* Wq      = (const float*)d_in[7];
    const float* bq      = (const float*)d_in[8];
    const float* Wk      = (const float*)d_in[9];
    const float* bk      = (const float*)d_in[10];
    const float* Wv      = (const float*)d_in[11];
    const float* bv      = (const float*)d_in[12];
    const float* Wo      = (const float*)d_in[13];
    const float* bo      = (const float*)d_in[14];
    const float* ln2_g   = (const float*)d_in[15];
    const float* ln2_b   = (const float*)d_in[16];
    const float* Wf1     = (const float*)d_in[17];
    const float* bf1     = (const float*)d_in[18];
    const float* Wf2     = (const float*)d_in[19];
    const float* bf2     = (const float*)d_in[20];
    const float* lnf_g   = (const float*)d_in[21];
    const float* lnf_b   = (const float*)d_in[22];
    const float* head_w  = (const float*)d_in[23];
    const float* head_b  = (const float*)d_in[24];
    float* out = (float*)d_out;

    float *x, *h, *q, *k, *v, *cls;
    __nv_bfloat16 *hh, *hl, *ah, *al, *fh, *fl, *ch, *cl, *wh, *wl, *pwh, *pwl;
    cudaGetSymbolAddress((void**)&x,   g_x);
    cudaGetSymbolAddress((void**)&h,   g_h);
    cudaGetSymbolAddress((void**)&q,   g_q);
    cudaGetSymbolAddress((void**)&k,   g_k);
    cudaGetSymbolAddress((void**)&v,   g_v);
    cudaGetSymbolAddress((void**)&cls, g_cls);
    cudaGetSymbolAddress((void**)&hh,  g_hh);
    cudaGetSymbolAddress((void**)&hl,  g_hl);
    cudaGetSymbolAddress((void**)&ah,  g_ah);
    cudaGetSymbolAddress((void**)&al,  g_al);
    cudaGetSymbolAddress((void**)&fh,  g_fh);
    cudaGetSymbolAddress((void**)&fl,  g_fl);
    cudaGetSymbolAddress((void**)&ch,  g_ch);
    cudaGetSymbolAddress((void**)&cl,  g_cl);
    cudaGetSymbolAddress((void**)&wh,  g_wh);
    cudaGetSymbolAddress((void**)&wl,  g_wl);
    cudaGetSymbolAddress((void**)&pwh, g_pwh);
    cudaGetSymbolAddress((void**)&pwl, g_pwl);

    cudaFuncSetAttribute(gemm_tc, cudaFuncAttributeMaxDynamicSharedMemorySize, GT_SMEM);
    cudaFuncSetAttribute(attn_kernel, cudaFuncAttributeMaxDynamicSharedMemorySize, ATTN_SMEM_BYTES);

    // ---- weight conversion (transpose + bf16 split), every launch ----
    {
        dim3 b256(256);
        wsplit_T<<<dim3(24, 24, NLAY), b256>>>(Wq,  wh + OFF_Q,  wl + OFF_Q,  768, 768,  (size_t)SZ_D2, LW);
        wsplit_T<<<dim3(24, 24, NLAY), b256>>>(Wk,  wh + OFF_K,  wl + OFF_K,  768, 768,  (size_t)SZ_D2, LW);
        wsplit_T<<<dim3(24, 24, NLAY), b256>>>(Wv,  wh + OFF_V,  wl + OFF_V,  768, 768,  (size_t)SZ_D2, LW);
        wsplit_T<<<dim3(24, 24, NLAY), b256>>>(Wo,  wh + OFF_O,  wl + OFF_O,  768, 768,  (size_t)SZ_D2, LW);
        wsplit_T<<<dim3(96, 24, NLAY), b256>>>(Wf1, wh + OFF_F1, wl + OFF_F1, 768, 3072, (size_t)SZ_DF, LW);
        wsplit_T<<<dim3(24, 96, NLAY), b256>>>(Wf2, wh + OFF_F2, wl + OFF_F2, 3072, 768, (size_t)SZ_DF, LW);
        split_ew<<<(SZ_D2 + 255) / 256, 256>>>(patch_w, pwh, pwl, SZ_D2);
    }

    // ---- patch embed ----
    im2col_split<<<(NPATCH * BD + 255) / 256, 256>>>(X, ch, cl);
    gemm_tc<<<dim3(6, 49), 256, GT_SMEM>>>(ch, cl, pwh, pwl, patch_b, nullptr,
                                           h, nullptr, nullptr, NPATCH, BD, BD, 0);
    assemble_k<<<(NTOK * BD + 255) / 256, 256>>>(h, cls_tok, pos_emb, x);

    const dim3 gD(6, 50);    // N=768,  M=6304
    const dim3 gF1(24, 50);  // N=3072

    for (int l = 0; l < NLAY; l++) {
        const __nv_bfloat16* wlh = wh + (size_t)l * LW;
        const __nv_bfloat16* wll = wl + (size_t)l * LW;

        ln_split<<<NTOK, 256>>>(x, ln1_g + l * BD, ln1_b + l * BD, hh, hl);

        gemm_tc<<<gD, 256, GT_SMEM>>>(hh, hl, wlh + OFF_Q, wll + OFF_Q, bq + l * BD, nullptr,
                                      q, nullptr, nullptr, NTOK, BD, BD, 0);
        gemm_tc<<<gD, 256, GT_SMEM>>>(hh, hl, wlh + OFF_K, wll + OFF_K, bk + l * BD, nullptr,
                                      k, nullptr, nullptr, NTOK, BD, BD, 0);
        gemm_tc<<<gD, 256, GT_SMEM>>>(hh, hl, wlh + OFF_V, wll + OFF_V, bv + l * BD, nullptr,
                                      v, nullptr, nullptr, NTOK, BD, BD, 0);

        attn_kernel<<<BATCH * NH, 256, ATTN_SMEM_BYTES>>>(q, k, v, ah, al);

        gemm_tc<<<gD, 256, GT_SMEM>>>(ah, al, wlh + OFF_O, wll + OFF_O, bo + l * BD, x,
                                      x, nullptr, nullptr, NTOK, BD, BD, 2);

        ln_split<<<NTOK, 256>>>(x, ln2_g + l * BD, ln2_b + l * BD, hh, hl);

        gemm_tc<<<gF1, 256, GT_SMEM>>>(hh, hl, wlh + OFF_F1, wll + OFF_F1, bf1 + l * FF, nullptr,
                                       nullptr, fh, fl, NTOK, FF, BD, 1);
        gemm_tc<<<gD, 256, GT_SMEM>>>(fh, fl, wlh + OFF_F2, wll + OFF_F2, bf2 + l * BD, x,
                                      x, nullptr, nullptr, NTOK, BD, FF, 2);
    }

    ln_kernel<<<BATCH, 256>>>(x, lnf_g, lnf_b, cls, (size_t)SEQ * BD);
    head_kernel<<<BATCH, 256>>>(cls, head_w, head_b, out);
}

// round 8
// speedup vs baseline: 2.3725x; 1.0161x over previous
#include <cuda_runtime.h>
#include <cuda_bf16.h>
#include <cstdint>
#include <cstddef>

// ---------------- problem constants ----------------
#define BATCH  32
#define SEQ    197
#define BD     768
#define NH     12
#define DH     64
#define NLAY   12
#define FF     3072
#define NCLS   1000
#define NTOK   (BATCH * SEQ)     // 6304
#define NPATCH (BATCH * 196)     // 6272
#define SPAD   200

#define SZ_D2  (768 * 768)
#define SZ_DF  (768 * 3072)
#define LW     ((size_t)(4 * SZ_D2) + (size_t)(2 * SZ_DF))
#define OFF_Q  ((size_t)0)
#define OFF_K  ((size_t)SZ_D2)
#define OFF_V  ((size_t)(2 * SZ_D2))
#define OFF_O  ((size_t)(3 * SZ_D2))
#define OFF_F1 ((size_t)(4 * SZ_D2))
#define OFF_F2 ((size_t)(4 * SZ_D2) + (size_t)SZ_DF)

// ---------------- device scratch (bss, no allocation) ----------------
__device__ __align__(128) float g_x[(size_t)NTOK * BD];
__device__ __align__(128) float g_h[(size_t)NTOK * BD];
__device__ __align__(128) float g_qkv[(size_t)3 * NTOK * BD];   // QKV out; FF2 split-K partials
__device__ __align__(128) float g_cls[(size_t)BATCH * BD];

__device__ __align__(128) __nv_bfloat16 g_hh[(size_t)NTOK * BD];
__device__ __align__(128) __nv_bfloat16 g_hl[(size_t)NTOK * BD];
__device__ __align__(128) __nv_bfloat16 g_ah[(size_t)NTOK * BD];
__device__ __align__(128) __nv_bfloat16 g_al[(size_t)NTOK * BD];
__device__ __align__(128) __nv_bfloat16 g_fh[(size_t)NTOK * FF];
__device__ __align__(128) __nv_bfloat16 g_fl[(size_t)NTOK * FF];
__device__ __align__(128) __nv_bfloat16 g_ch[(size_t)NPATCH * BD];
__device__ __align__(128) __nv_bfloat16 g_cl[(size_t)NPATCH * BD];
__device__ __align__(128) __nv_bfloat16 g_wh[(size_t)NLAY * LW];
__device__ __align__(128) __nv_bfloat16 g_wl[(size_t)NLAY * LW];
__device__ __align__(128) __nv_bfloat16 g_pwh[(size_t)SZ_D2];
__device__ __align__(128) __nv_bfloat16 g_pwl[(size_t)SZ_D2];

// ---------------- PTX helpers (generic compute_103-safe) ----------------
__device__ __forceinline__ uint32_t smem_u32(const void* p) {
    uint32_t a;
    asm("{ .reg .u64 t; cvta.to.shared.u64 t, %1; cvt.u32.u64 %0, t; }" : "=r"(a) : "l"(p));
    return a;
}

__device__ __forceinline__ void cp16(uint32_t dst, const void* src) {
    asm volatile("cp.async.cg.shared.global [%0], [%1], 16;" :: "r"(dst), "l"(src) : "memory");
}
#define CP_COMMIT() asm volatile("cp.async.commit_group;" ::: "memory")
#define CP_WAIT1()  asm volatile("cp.async.wait_group 1;" ::: "memory")
#define CP_WAIT0()  asm volatile("cp.async.wait_group 0;" ::: "memory")

__device__ __forceinline__ void ldsm4(uint32_t* r, uint32_t addr) {
    asm volatile("ldmatrix.sync.aligned.m8n8.x4.shared.b16 {%0,%1,%2,%3}, [%4];"
        : "=r"(r[0]), "=r"(r[1]), "=r"(r[2]), "=r"(r[3]) : "r"(addr));
}

__device__ __forceinline__ void mma_bf16(float* d, const uint32_t* a, const uint32_t* b) {
    asm volatile(
        "mma.sync.aligned.m16n8k16.row.col.f32.bf16.bf16.f32 "
        "{%0,%1,%2,%3}, {%4,%5,%6,%7}, {%8,%9}, {%0,%1,%2,%3};"
        : "+f"(d[0]), "+f"(d[1]), "+f"(d[2]), "+f"(d[3])
        : "r"(a[0]), "r"(a[1]), "r"(a[2]), "r"(a[3]), "r"(b[0]), "r"(b[1]));
}

// ---------------- tensor-core split-bf16 GEMM ----------------
// D[m,n] = sum_k A[m,k]*B[n,k]  via Ahi*Bhi + Ahi*Blo + Alo*Bhi (bf16, fp32 acc)
// mode 0: Cf = D + bias
// mode 1: gelu(D + bias) -> (Chi, Clo) split bf16
// mode 2: Cf = D + bias + res
// mode 3: QKV partitioned: out part = bn/768 -> Cf + part*M*768, stride 768,
//         bias selected from {bias, bias2, bias3}
// mode 4: raw split-K partial: Cf + blockIdx.z*M*N = D (no bias)
#define TILE_B  10240                // 128 rows * 80B (32 bf16 + 8 pad)
#define STAGE_B (4 * TILE_B)         // Ah, Al, Bh, Bl
#define GT_SMEM (2 * STAGE_B)        // 81920 double buffered

__global__ __launch_bounds__(256, 2) void gemm_tc(
    const __nv_bfloat16* __restrict__ Ahi, const __nv_bfloat16* __restrict__ Alo,
    const __nv_bfloat16* __restrict__ Bhi, const __nv_bfloat16* __restrict__ Blo,
    const float* __restrict__ bias, const float* __restrict__ bias2,
    const float* __restrict__ bias3, const float* __restrict__ res,
    float* __restrict__ Cf, __nv_bfloat16* __restrict__ Chi, __nv_bfloat16* __restrict__ Clo,
    int M, int N, int Kloc, int Kstride, int mode)
{
    extern __shared__ __align__(128) char smem[];
    const uint32_t sb = smem_u32(smem);
    const int tid = threadIdx.x, wid = tid >> 5, lane = tid & 31;
    const int bm = blockIdx.y * 128, bn = blockIdx.x * 128;
    const int wm = (wid & 1) * 64, wn = (wid >> 1) * 32;
    const size_t kz = (size_t)blockIdx.z * (size_t)Kloc;

    float acc[4][4][4];
#pragma unroll
    for (int mt = 0; mt < 4; mt++)
#pragma unroll
        for (int nt = 0; nt < 4; nt++)
#pragma unroll
            for (int e = 0; e < 4; e++) acc[mt][nt][e] = 0.f;

    const __nv_bfloat16* src[4] = {Ahi, Alo, Bhi, Blo};
    const int NKs = Kloc >> 5;

    auto load_stage = [&](int st, int k0) {
        uint32_t base = sb + (uint32_t)st * STAGE_B;
        size_t kg = kz + (size_t)k0;
#pragma unroll
        for (int t = 0; t < 4; t++) {
#pragma unroll
            for (int j = 0; j < 2; j++) {
                int cid = tid + (j << 8);
                int row = cid >> 2, chk = cid & 3;
                int rg = (t < 2) ? min(bm + row, M - 1) : (bn + row);
                cp16(base + (uint32_t)(t * TILE_B + row * 80 + chk * 16),
                     src[t] + (size_t)rg * Kstride + kg + chk * 8);
            }
        }
        CP_COMMIT();
    };

    load_stage(0, 0);
    for (int i = 0; i < NKs; i++) {
        if (i + 1 < NKs) { load_stage((i + 1) & 1, (i + 1) << 5); CP_WAIT1(); }
        else            { CP_WAIT0(); }
        __syncthreads();

        const uint32_t stb = sb + (uint32_t)(i & 1) * STAGE_B;
        const int g = lane >> 3, r = lane & 7;

#pragma unroll
        for (int k16 = 0; k16 < 2; k16++) {
            // B fragments (hi & lo) resident across all 3 product terms
            uint32_t bh[4][2], bl[4][2];
#pragma unroll
            for (int nt2 = 0; nt2 < 2; nt2++) {
                uint32_t b4[4];
                int nloc = wn + nt2 * 16 + (g >> 1) * 8 + r;
                int kb_ = k16 * 16 + (g & 1) * 8;
                ldsm4(b4, stb + (uint32_t)(2 * TILE_B + nloc * 80 + kb_ * 2));
                bh[nt2 * 2 + 0][0] = b4[0]; bh[nt2 * 2 + 0][1] = b4[1];
                bh[nt2 * 2 + 1][0] = b4[2]; bh[nt2 * 2 + 1][1] = b4[3];
                ldsm4(b4, stb + (uint32_t)(3 * TILE_B + nloc * 80 + kb_ * 2));
                bl[nt2 * 2 + 0][0] = b4[0]; bl[nt2 * 2 + 0][1] = b4[1];
                bl[nt2 * 2 + 1][0] = b4[2]; bl[nt2 * 2 + 1][1] = b4[3];
            }
#pragma unroll
            for (int mt = 0; mt < 4; mt++) {
                uint32_t a4[4];
                int mloc = wm + mt * 16 + (g & 1) * 8 + r;
                int ka_ = k16 * 16 + (g >> 1) * 8;
                ldsm4(a4, stb + (uint32_t)(0 * TILE_B + mloc * 80 + ka_ * 2));
#pragma unroll
                for (int nt = 0; nt < 4; nt++) mma_bf16(acc[mt][nt], a4, bh[nt]);
#pragma unroll
                for (int nt = 0; nt < 4; nt++) mma_bf16(acc[mt][nt], a4, bl[nt]);
                ldsm4(a4, stb + (uint32_t)(1 * TILE_B + mloc * 80 + ka_ * 2));
#pragma unroll
                for (int nt = 0; nt < 4; nt++) mma_bf16(acc[mt][nt], a4, bh[nt]);
            }
        }
        __syncthreads();
    }

    // ---- epilogue: register-direct ----
    float* outF = Cf;
    int Nout = N;
    int nbase = bn;
    const float* bb = bias;
    if (mode == 3) {
        int part = bn / 768;
        outF = Cf + (size_t)part * M * 768;
        nbase = bn - part * 768;
        Nout = 768;
        bb = (part == 0) ? bias : (part == 1) ? bias2 : bias3;
    } else if (mode == 4) {
        outF = Cf + (size_t)blockIdx.z * M * N;
    }

    const int r0 = lane >> 2, c0 = (lane & 3) * 2;
    float bv[4][2];
#pragma unroll
    for (int nt = 0; nt < 4; nt++) {
        int n = nbase + wn + nt * 8 + c0;
        bv[nt][0] = bb ? __ldg(bb + n) : 0.f;
        bv[nt][1] = bb ? __ldg(bb + n + 1) : 0.f;
    }

#pragma unroll
    for (int mt = 0; mt < 4; mt++) {
#pragma unroll
        for (int half = 0; half < 2; half++) {
            int m = bm + wm + mt * 16 + half * 8 + r0;
            if (m >= M) continue;
#pragma unroll
            for (int nt = 0; nt < 4; nt++) {
                int n = nbase + wn + nt * 8 + c0;
                float v0 = acc[mt][nt][half * 2 + 0] + bv[nt][0];
                float v1 = acc[mt][nt][half * 2 + 1] + bv[nt][1];
                if (mode == 1) {
                    v0 = 0.5f * v0 * (1.f + erff(v0 * 0.70710678118654752440f));
                    v1 = 0.5f * v1 * (1.f + erff(v1 * 0.70710678118654752440f));
                    __nv_bfloat16 h0 = __float2bfloat16(v0);
                    __nv_bfloat16 h1 = __float2bfloat16(v1);
                    __nv_bfloat162 hi; hi.x = h0; hi.y = h1;
                    __nv_bfloat162 lo;
                    lo.x = __float2bfloat16(v0 - __bfloat162float(h0));
                    lo.y = __float2bfloat16(v1 - __bfloat162float(h1));
                    *(__nv_bfloat162*)(Chi + (size_t)m * N + n) = hi;
                    *(__nv_bfloat162*)(Clo + (size_t)m * N + n) = lo;
                } else {
                    if (mode == 2) {
                        float2 rr = *(const float2*)(res + (size_t)m * N + n);
                        v0 += rr.x; v1 += rr.y;
                    }
                    float2 o; o.x = v0; o.y = v1;
                    *(float2*)(outF + (size_t)m * Nout + n) = o;
                }
            }
        }
    }
}

// ---------------- split-K combine: x += p0 + p1 + bias ----------------
__global__ void combine_k(float* __restrict__ x, const float* __restrict__ p0,
                          const float* __restrict__ p1, const float* __restrict__ bias)
{
    int i = blockIdx.x * blockDim.x + threadIdx.x;
    if (i < NTOK * BD) {
        x[i] += p0[i] + p1[i] + bias[i % BD];
    }
}

// ---------------- weight transpose + split: W[K,N] fp32 -> (hi,lo)[N,K] bf16 ----------------
__global__ __launch_bounds__(256) void wsplit_T(
    const float* __restrict__ src, __nv_bfloat16* __restrict__ dh, __nv_bfloat16* __restrict__ dl,
    int K, int N, size_t ls_in, size_t ls_out)
{
    __shared__ float t[32][33];
    const int l = blockIdx.z;
    const int kb = blockIdx.y << 5, nb = blockIdx.x << 5;
    const int tx = threadIdx.x & 31, ty = threadIdx.x >> 5;
    const float* s = src + (size_t)l * ls_in;
#pragma unroll
    for (int r = 0; r < 4; r++) {
        int row = ty + (r << 3);
        t[row][tx] = s[(size_t)(kb + row) * N + nb + tx];
    }
    __syncthreads();
    __nv_bfloat16* oh = dh + (size_t)l * ls_out;
    __nv_bfloat16* ol = dl + (size_t)l * ls_out;
#pragma unroll
    for (int r = 0; r < 4; r++) {
        int row = ty + (r << 3);
        float v = t[tx][row];
        __nv_bfloat16 h = __float2bfloat16(v);
        size_t o = (size_t)(nb + row) * K + kb + tx;
        oh[o] = h;
        ol[o] = __float2bfloat16(v - __bfloat162float(h));
    }
}

__global__ void split_ew(const float* __restrict__ s, __nv_bfloat16* __restrict__ dh,
                         __nv_bfloat16* __restrict__ dl, int n)
{
    int i = blockIdx.x * blockDim.x + threadIdx.x;
    if (i < n) {
        float v = s[i];
        __nv_bfloat16 h = __float2bfloat16(v);
        dh[i] = h;
        dl[i] = __float2bfloat16(v - __bfloat162float(h));
    }
}

// ---------------- layernorm ----------------
__device__ __forceinline__ float block_sum(float v, float* red)
{
#pragma unroll
    for (int o = 16; o; o >>= 1) v += __shfl_xor_sync(0xffffffffu, v, o);
    int w = threadIdx.x >> 5;
    if ((threadIdx.x & 31) == 0) red[w] = v;
    __syncthreads();
    float t = 0.f;
    if (threadIdx.x < 32) {
        t = (threadIdx.x < 8) ? red[threadIdx.x] : 0.f;
#pragma unroll
        for (int o = 4; o; o >>= 1) t += __shfl_xor_sync(0xffffffffu, t, o);
        if (threadIdx.x == 0) red[0] = t;
    }
    __syncthreads();
    float r = red[0];
    __syncthreads();
    return r;
}

__global__ __launch_bounds__(256) void ln_kernel(
    const float* __restrict__ X, const float* __restrict__ g,
    const float* __restrict__ bb, float* __restrict__ out, size_t in_stride)
{
    __shared__ float red[8];
    const int tid = threadIdx.x;
    const float* xr = X + (size_t)blockIdx.x * in_stride;
    float v0 = xr[tid], v1 = xr[tid + 256], v2 = xr[tid + 512];
    float s = block_sum(v0 + v1 + v2, red);
    float mean = s * (1.f / 768.f);
    float d0 = v0 - mean, d1 = v1 - mean, d2 = v2 - mean;
    float sq = block_sum(d0 * d0 + d1 * d1 + d2 * d2, red);
    float rstd = rsqrtf(sq * (1.f / 768.f) + 1e-5f);
    float* orow = out + (size_t)blockIdx.x * BD;
    orow[tid]       = d0 * rstd * g[tid]       + bb[tid];
    orow[tid + 256] = d1 * rstd * g[tid + 256] + bb[tid + 256];
    orow[tid + 512] = d2 * rstd * g[tid + 512] + bb[tid + 512];
}

__global__ __launch_bounds__(256) void ln_split(
    const float* __restrict__ X, const float* __restrict__ g,
    const float* __restrict__ bb, __nv_bfloat16* __restrict__ oh,
    __nv_bfloat16* __restrict__ ol)
{
    __shared__ float red[8];
    const int tid = threadIdx.x;
    const float* xr = X + (size_t)blockIdx.x * BD;
    float v0 = xr[tid], v1 = xr[tid + 256], v2 = xr[tid + 512];
    float s = block_sum(v0 + v1 + v2, red);
    float mean = s * (1.f / 768.f);
    float d0 = v0 - mean, d1 = v1 - mean, d2 = v2 - mean;
    float sq = block_sum(d0 * d0 + d1 * d1 + d2 * d2, red);
    float rstd = rsqrtf(sq * (1.f / 768.f) + 1e-5f);
    size_t ro = (size_t)blockIdx.x * BD;
#pragma unroll
    for (int j = 0; j < 3; j++) {
        float d = (j == 0) ? d0 : (j == 1) ? d1 : d2;
        int c = tid + j * 256;
        float y = d * rstd * g[c] + bb[c];
        __nv_bfloat16 h = __float2bfloat16(y);
        oh[ro + c] = h;
        ol[ro + c] = __float2bfloat16(y - __bfloat162float(h));
    }
}

// ---------------- attention ----------------
#define ATTN_SMEM_FLOATS (SPAD * 65 * 2 + 8 * SPAD)
#define ATTN_SMEM_BYTES  (ATTN_SMEM_FLOATS * 4)   // 110400 -> 2 CTAs/SM

__global__ __launch_bounds__(256) void attn_kernel(
    const float* __restrict__ Q, const float* __restrict__ K,
    const float* __restrict__ V, __nv_bfloat16* __restrict__ Oh,
    __nv_bfloat16* __restrict__ Ol)
{
    extern __shared__ float sm[];
    float* Ks = sm;
    float* Vs = Ks + SPAD * 65;
    float* Ps = Vs + SPAD * 65;

    const int bh = blockIdx.x;
    const int b = bh / NH, h = bh % NH;
    const size_t base = (size_t)b * SEQ * BD + (size_t)h * DH;
    const int tid = threadIdx.x;

    for (int i = tid; i < SPAD * 65; i += 256) {
        int s = i / 65, d = i - s * 65;
        float kv = 0.f, vv = 0.f;
        if (s < SEQ && d < DH) {
            kv = K[base + (size_t)s * BD + d];
            vv = V[base + (size_t)s * BD + d];
        }
        Ks[i] = kv;
        Vs[i] = vv;
    }
    __syncthreads();

    const int warp = tid >> 5, lane = tid & 31;
    float* Pw = Ps + warp * SPAD;

    for (int s = warp; s < SEQ; s += 8) {
        const float* q = Q + base + (size_t)s * BD;
        float acc[7];
#pragma unroll
        for (int j = 0; j < 7; j++) acc[j] = 0.f;

#pragma unroll 8
        for (int d = 0; d < DH; d++) {
            float qd = __ldg(q + d);
#pragma unroll
            for (int j = 0; j < 7; j++) {
                int t = lane + j * 32;      // reads past SEQ stay inside the dyn-smem alloc; masked below
                acc[j] += qd * Ks[t * 65 + d];
            }
        }
#pragma unroll
        for (int j = 0; j < 7; j++) acc[j] *= 0.125f;

        float mx = -1e30f;
#pragma unroll
        for (int j = 0; j < 7; j++)
            if (lane + j * 32 < SEQ) mx = fmaxf(mx, acc[j]);
#pragma unroll
        for (int o = 16; o; o >>= 1) mx = fmaxf(mx, __shfl_xor_sync(0xffffffffu, mx, o));

        float sum = 0.f;
        float ex[7];
#pragma unroll
        for (int j = 0; j < 7; j++) {
            int t = lane + j * 32;
            float e = (t < SEQ) ? __expf(acc[j] - mx) : 0.f;
            ex[j] = e;
            sum += e;
        }
#pragma unroll
        for (int o = 16; o; o >>= 1) sum += __shfl_xor_sync(0xffffffffu, sum, o);
        float inv = 1.f / sum;

#pragma unroll
        for (int j = 0; j < 7; j++) {
            int t = lane + j * 32;
            if (t < SEQ) Pw[t] = ex[j] * inv;
        }
        __syncwarp();

        float o0 = 0.f, o1 = 0.f;
        for (int t = 0; t < SEQ; t++) {
            float p = Pw[t];
            o0 += p * Vs[t * 65 + lane];
            o1 += p * Vs[t * 65 + lane + 32];
        }
        {
            __nv_bfloat16 h0 = __float2bfloat16(o0);
            Oh[base + (size_t)s * BD + lane] = h0;
            Ol[base + (size_t)s * BD + lane] = __float2bfloat16(o0 - __bfloat162float(h0));
            __nv_bfloat16 h1 = __float2bfloat16(o1);
            Oh[base + (size_t)s * BD + lane + 32] = h1;
            Ol[base + (size_t)s * BD + lane + 32] = __float2bfloat16(o1 - __bfloat162float(h1));
        }
        __syncwarp();
    }
}

// ---------------- small kernels ----------------
__global__ void im2col_split(const float* __restrict__ X, __nv_bfloat16* __restrict__ ch,
                             __nv_bfloat16* __restrict__ cl)
{
    int idx = blockIdx.x * blockDim.x + threadIdx.x;
    if (idx >= NPATCH * BD) return;
    int m = idx / BD, kk = idx - m * BD;
    int b = m / 196, hw = m - b * 196;
    int ph = hw / 14, pw = hw - ph * 14;
    int c = kk >> 8, r = kk & 255, p = r >> 4, q = r & 15;
    float v = X[((size_t)(b * 3 + c) * 224 + ph * 16 + p) * 224 + pw * 16 + q];
    __nv_bfloat16 h = __float2bfloat16(v);
    ch[idx] = h;
    cl[idx] = __float2bfloat16(v - __bfloat162float(h));
}

__global__ void assemble_k(const float* __restrict__ patches, const float* __restrict__ cls,
                           const float* __restrict__ pos, float* __restrict__ x)
{
    int idx = blockIdx.x * blockDim.x + threadIdx.x;
    if (idx >= NTOK * BD) return;
    int d = idx % BD;
    int t = idx / BD;
    int b = t / SEQ, s = t - b * SEQ;
    float v = (s == 0) ? cls[d] : patches[((size_t)b * 196 + (s - 1)) * BD + d];
    x[idx] = v + pos[(size_t)s * BD + d];
}

__global__ __launch_bounds__(256) void head_kernel(
    const float* __restrict__ xc, const float* __restrict__ W,
    const float* __restrict__ bias, float* __restrict__ out)
{
    __shared__ float xs[BD];
    const int b = blockIdx.x;
    for (int i = threadIdx.x; i < BD; i += 256) xs[i] = xc[(size_t)b * BD + i];
    __syncthreads();

    const int n0 = threadIdx.x;
    float acc[4] = {0.f, 0.f, 0.f, 0.f};
    for (int k = 0; k < BD; k++) {
        float xv = xs[k];
#pragma unroll
        for (int j = 0; j < 4; j++) {
            int n = n0 + j * 256;
            if (n < NCLS) acc[j] += xv * W[(size_t)k * NCLS + n];
        }
    }
#pragma unroll
    for (int j = 0; j < 4; j++) {
        int n = n0 + j * 256;
        if (n < NCLS) out[(size_t)b * NCLS + n] = acc[j] + bias[n];
    }
}

// ---------------- launch ----------------
extern "C" void kernel_launch(void* const* d_in, const int* in_sizes, int n_in,
                              void* d_out, int out_size)
{
    const float* X       = (const float*)d_in[0];
    const float* patch_w = (const float*)d_in[1];
    const float* patch_b = (const float*)d_in[2];
    const float* cls_tok = (const float*)d_in[3];
    const float* pos_emb = (const float*)d_in[4];
    const float* ln1_g   = (const float*)d_in[5];
    const float* ln1_b   = (const float*)d_in[6];
    const float* Wq      = (const float*)d_in[7];
    const float* bq      = (const float*)d_in[8];
    const float* Wk      = (const float*)d_in[9];
    const float* bk      = (const float*)d_in[10];
    const float* Wv      = (const float*)d_in[11];
    const float* bv      = (const float*)d_in[12];
    const float* Wo      = (const float*)d_in[13];
    const float* bo      = (const float*)d_in[14];
    const float* ln2_g   = (const float*)d_in[15];
    const float* ln2_b   = (const float*)d_in[16];
    const float* Wf1     = (const float*)d_in[17];
    const float* bf1     = (const float*)d_in[18];
    const float* Wf2     = (const float*)d_in[19];
    const float* bf2     = (const float*)d_in[20];
    const float* lnf_g   = (const float*)d_in[21];
    const float* lnf_b   = (const float*)d_in[22];
    const float* head_w  = (const float*)d_in[23];
    const float* head_b  = (const float*)d_in[24];
    float* out = (float*)d_out;

    float *x, *h, *qkv, *cls;
    __nv_bfloat16 *hh, *hl, *ah, *al, *fh, *fl, *ch, *cl, *wh, *wl, *pwh, *pwl;
    cudaGetSymbolAddress((void**)&x,   g_x);
    cudaGetSymbolAddress((void**)&h,   g_h);
    cudaGetSymbolAddress((void**)&qkv, g_qkv);
    cudaGetSymbolAddress((void**)&cls, g_cls);
    cudaGetSymbolAddress((void**)&hh,  g_hh);
    cudaGetSymbolAddress((void**)&hl,  g_hl);
    cudaGetSymbolAddress((void**)&ah,  g_ah);
    cudaGetSymbolAddress((void**)&al,  g_al);
    cudaGetSymbolAddress((void**)&fh,  g_fh);
    cudaGetSymbolAddress((void**)&fl,  g_fl);
    cudaGetSymbolAddress((void**)&ch,  g_ch);
    cudaGetSymbolAddress((void**)&cl,  g_cl);
    cudaGetSymbolAddress((void**)&wh,  g_wh);
    cudaGetSymbolAddress((void**)&wl,  g_wl);
    cudaGetSymbolAddress((void**)&pwh, g_pwh);
    cudaGetSymbolAddress((void**)&pwl, g_pwl);

    cudaFuncSetAttribute(gemm_tc, cudaFuncAttributeMaxDynamicSharedMemorySize, GT_SMEM);
    cudaFuncSetAttribute(attn_kernel, cudaFuncAttributeMaxDynamicSharedMemorySize, ATTN_SMEM_BYTES);

    // ---- weight conversion (transpose + bf16 split) ----
    {
        dim3 b256(256);
        wsplit_T<<<dim3(24, 24, NLAY), b256>>>(Wq,  wh + OFF_Q,  wl + OFF_Q,  768, 768,  (size_t)SZ_D2, LW);
        wsplit_T<<<dim3(24, 24, NLAY), b256>>>(Wk,  wh + OFF_K,  wl + OFF_K,  768, 768,  (size_t)SZ_D2, LW);
        wsplit_T<<<dim3(24, 24, NLAY), b256>>>(Wv,  wh + OFF_V,  wl + OFF_V,  768, 768,  (size_t)SZ_D2, LW);
        wsplit_T<<<dim3(24, 24, NLAY), b256>>>(Wo,  wh + OFF_O,  wl + OFF_O,  768, 768,  (size_t)SZ_D2, LW);
        wsplit_T<<<dim3(96, 24, NLAY), b256>>>(Wf1, wh + OFF_F1, wl + OFF_F1, 768, 3072, (size_t)SZ_DF, LW);
        wsplit_T<<<dim3(24, 96, NLAY), b256>>>(Wf2, wh + OFF_F2, wl + OFF_F2, 3072, 768, (size_t)SZ_DF, LW);
        split_ew<<<(SZ_D2 + 255) / 256, 256>>>(patch_w, pwh, pwl, SZ_D2);
    }

    // ---- patch embed (6x49 = 294 CTAs: single wave) ----
    im2col_split<<<(NPATCH * BD + 255) / 256, 256>>>(X, ch, cl);
    gemm_tc<<<dim3(6, 49), 256, GT_SMEM>>>(ch, cl, pwh, pwl, patch_b, nullptr, nullptr, nullptr,
                                           h, nullptr, nullptr, NPATCH, BD, BD, BD, 0);
    assemble_k<<<(NTOK * BD + 255) / 256, 256>>>(h, cls_tok, pos_emb, x);

    const dim3 gQKV(18, 50);       // N=2304 merged
    const dim3 gD(6, 50);          // N=768
    const dim3 gF1(24, 50);        // N=3072
    const dim3 gF2(6, 50, 2);      // N=768, split-K=2

    float* qF = qkv;
    float* kF = qkv + (size_t)NTOK * BD;
    float* vF = qkv + (size_t)2 * NTOK * BD;

    for (int l = 0; l < NLAY; l++) {
        const __nv_bfloat16* wlh = wh + (size_t)l * LW;
        const __nv_bfloat16* wll = wl + (size_t)l * LW;

        ln_split<<<NTOK, 256>>>(x, ln1_g + l * BD, ln1_b + l * BD, hh, hl);

        // merged QKV: one GEMM, partitioned epilogue
        gemm_tc<<<gQKV, 256, GT_SMEM>>>(hh, hl, wlh + OFF_Q, wll + OFF_Q,
                                        bq + l * BD, bk + l * BD, bv + l * BD, nullptr,
                                        qkv, nullptr, nullptr, NTOK, 3 * BD, BD, BD, 3);

        attn_kernel<<<BATCH * NH, 256, ATTN_SMEM_BYTES>>>(qF, kF, vF, ah, al);

        gemm_tc<<<gD, 256, GT_SMEM>>>(ah, al, wlh + OFF_O, wll + OFF_O,
                                      bo + l * BD, nullptr, nullptr, x,
                                      x, nullptr, nullptr, NTOK, BD, BD, BD, 2);

        ln_split<<<NTOK, 256>>>(x, ln2_g + l * BD, ln2_b + l * BD, hh, hl);

        gemm_tc<<<gF1, 256, GT_SMEM>>>(hh, hl, wlh + OFF_F1, wll + OFF_F1,
                                       bf1 + l * FF, nullptr, nullptr, nullptr,
                                       nullptr, fh, fl, NTOK, FF, BD, BD, 1);

        // FF2 split-K=2: partials into qkv scratch (free during MLP phase), then combine
        gemm_tc<<<gF2, 256, GT_SMEM>>>(fh, fl, wlh + OFF_F2, wll + OFF_F2,
                                       nullptr, nullptr, nullptr, nullptr,
                                       qkv, nullptr, nullptr, NTOK, BD, FF / 2, FF, 4);
        combine_k<<<(NTOK * BD + 255) / 256, 256>>>(x, qF, kF, bf2 + l * BD);
    }

    ln_kernel<<<BATCH, 256>>>(x, lnf_g, lnf_b, cls, (size_t)SEQ * BD);
    head_kernel<<<BATCH, 256>>>(cls, head_w, head_b, out);
}

// round 12
// speedup vs baseline: 2.9528x; 1.2446x over previous
#include <cuda_runtime.h>
#include <cuda_bf16.h>
#include <cstdint>
#include <cstddef>

// ---------------- problem constants ----------------
#define BATCH  32
#define SEQ    197
#define BD     768
#define NH     12
#define DH     64
#define NLAY   12
#define FF     3072
#define NCLS   1000
#define NTOK   (BATCH * SEQ)     // 6304
#define NPATCH (BATCH * 196)     // 6272
#define SPAD   200

#define SZ_D2  (768 * 768)
#define SZ_DF  (768 * 3072)
#define LW     ((size_t)(4 * SZ_D2) + (size_t)(2 * SZ_DF))
#define OFF_Q  ((size_t)0)
#define OFF_K  ((size_t)SZ_D2)
#define OFF_V  ((size_t)(2 * SZ_D2))
#define OFF_O  ((size_t)(3 * SZ_D2))
#define OFF_F1 ((size_t)(4 * SZ_D2))
#define OFF_F2 ((size_t)(4 * SZ_D2) + (size_t)SZ_DF)

// ---------------- device scratch (bss, no allocation) ----------------
__device__ __align__(128) float g_x[(size_t)NTOK * BD];
__device__ __align__(128) float g_h[(size_t)NTOK * BD];
__device__ __align__(128) float g_qkv[(size_t)3 * NTOK * BD];   // QKV out; FF2 split-K partials
__device__ __align__(128) float g_cls[(size_t)BATCH * BD];

__device__ __align__(128) __nv_bfloat16 g_hh[(size_t)NTOK * BD];
__device__ __align__(128) __nv_bfloat16 g_hl[(size_t)NTOK * BD];
__device__ __align__(128) __nv_bfloat16 g_ah[(size_t)NTOK * BD];
__device__ __align__(128) __nv_bfloat16 g_al[(size_t)NTOK * BD];
__device__ __align__(128) __nv_bfloat16 g_fh[(size_t)NTOK * FF];
__device__ __align__(128) __nv_bfloat16 g_fl[(size_t)NTOK * FF];
__device__ __align__(128) __nv_bfloat16 g_ch[(size_t)NPATCH * BD];
__device__ __align__(128) __nv_bfloat16 g_cl[(size_t)NPATCH * BD];
__device__ __align__(128) __nv_bfloat16 g_wh[(size_t)NLAY * LW];
__device__ __align__(128) __nv_bfloat16 g_wl[(size_t)NLAY * LW];
__device__ __align__(128) __nv_bfloat16 g_pwh[(size_t)SZ_D2];
__device__ __align__(128) __nv_bfloat16 g_pwl[(size_t)SZ_D2];

// ---------------- PTX helpers (generic compute_103-safe) ----------------
__device__ __forceinline__ uint32_t smem_u32(const void* p) {
    uint32_t a;
    asm("{ .reg .u64 t; cvta.to.shared.u64 t, %1; cvt.u32.u64 %0, t; }" : "=r"(a) : "l"(p));
    return a;
}

__device__ __forceinline__ void cp16(uint32_t dst, const void* src) {
    asm volatile("cp.async.cg.shared.global [%0], [%1], 16;" :: "r"(dst), "l"(src) : "memory");
}
#define CP_COMMIT() asm volatile("cp.async.commit_group;" ::: "memory")
#define CP_WAIT0()  asm volatile("cp.async.wait_group 0;" ::: "memory")

__device__ __forceinline__ void ldsm4(uint32_t* r, uint32_t addr) {
    asm volatile("ldmatrix.sync.aligned.m8n8.x4.shared.b16 {%0,%1,%2,%3}, [%4];"
        : "=r"(r[0]), "=r"(r[1]), "=r"(r[2]), "=r"(r[3]) : "r"(addr));
}

__device__ __forceinline__ void mma_bf16(float* d, const uint32_t* a, const uint32_t* b) {
    asm volatile(
        "mma.sync.aligned.m16n8k16.row.col.f32.bf16.bf16.f32 "
        "{%0,%1,%2,%3}, {%4,%5,%6,%7}, {%8,%9}, {%0,%1,%2,%3};"
        : "+f"(d[0]), "+f"(d[1]), "+f"(d[2]), "+f"(d[3])
        : "r"(a[0]), "r"(a[1]), "r"(a[2]), "r"(a[3]), "r"(b[0]), "r"(b[1]));
}

// ---------------- tensor-core split-bf16 GEMM ----------------
// D[m,n] = sum_k A[m,k]*B[n,k]  via Ahi*Bhi + Ahi*Blo + Alo*Bhi (bf16, fp32 acc)
// mode 0: Cf = D + bias
// mode 1: gelu(D + bias) -> (Chi, Clo) split bf16
// mode 2: Cf = D + bias + res
// mode 3: QKV partitioned epilogue
// mode 4: raw split-K partial: Cf + blockIdx.z*M*N = D (no bias)
#define TILE_B  10240                // 128 rows * 80B (32 bf16 + 8 pad)
#define STAGE_B (4 * TILE_B)         // Ah, Al, Bh, Bl
#define GT_SMEM (2 * STAGE_B)        // 81920 double buffered

__global__ __launch_bounds__(256, 2) void gemm_tc(
    const __nv_bfloat16* __restrict__ Ahi, const __nv_bfloat16* __restrict__ Alo,
    const __nv_bfloat16* __restrict__ Bhi, const __nv_bfloat16* __restrict__ Blo,
    const float* __restrict__ bias, const float* __restrict__ bias2,
    const float* __restrict__ bias3, const float* __restrict__ res,
    float* __restrict__ Cf, __nv_bfloat16* __restrict__ Chi, __nv_bfloat16* __restrict__ Clo,
    int M, int N, int Kloc, int Kstride, int mode)
{
    extern __shared__ __align__(128) char smem[];
    const uint32_t sb = smem_u32(smem);
    const int tid = threadIdx.x, wid = tid >> 5, lane = tid & 31;
    const int bm = blockIdx.y * 128, bn = blockIdx.x * 128;
    const int wm = (wid & 1) * 64, wn = (wid >> 1) * 32;
    const size_t kz = (size_t)blockIdx.z * (size_t)Kloc;

    float acc[4][4][4];
#pragma unroll
    for (int mt = 0; mt < 4; mt++)
#pragma unroll
        for (int nt = 0; nt < 4; nt++)
#pragma unroll
            for (int e = 0; e < 4; e++) acc[mt][nt][e] = 0.f;

    const __nv_bfloat16* src[4] = {Ahi, Alo, Bhi, Blo};
    const int NKs = Kloc >> 5;

    auto load_stage = [&](int st, int k0) {
        uint32_t base = sb + (uint32_t)st * STAGE_B;
        size_t kg = kz + (size_t)k0;
#pragma unroll
        for (int t = 0; t < 4; t++) {
#pragma unroll
            for (int j = 0; j < 2; j++) {
                int cid = tid + (j << 8);
                int row = cid >> 2, chk = cid & 3;
                int rg = (t < 2) ? min(bm + row, M - 1) : (bn + row);
                cp16(base + (uint32_t)(t * TILE_B + row * 80 + chk * 16),
                     src[t] + (size_t)rg * Kstride + kg + chk * 8);
            }
        }
        CP_COMMIT();
    };

    load_stage(0, 0);
    for (int i = 0; i < NKs; i++) {
        CP_WAIT0();
        __syncthreads();   // single barrier: data-visible + prev-buffer reads done
        if (i + 1 < NKs) load_stage((i + 1) & 1, (i + 1) << 5);

        const uint32_t stb = sb + (uint32_t)(i & 1) * STAGE_B;
        const int g = lane >> 3, r = lane & 7;

#pragma unroll
        for (int k16 = 0; k16 < 2; k16++) {
            uint32_t bh[4][2], bl[4][2];
#pragma unroll
            for (int nt2 = 0; nt2 < 2; nt2++) {
                uint32_t b4[4];
                int nloc = wn + nt2 * 16 + (g >> 1) * 8 + r;
                int kb_ = k16 * 16 + (g & 1) * 8;
                ldsm4(b4, stb + (uint32_t)(2 * TILE_B + nloc * 80 + kb_ * 2));
                bh[nt2 * 2 + 0][0] = b4[0]; bh[nt2 * 2 + 0][1] = b4[1];
                bh[nt2 * 2 + 1][0] = b4[2]; bh[nt2 * 2 + 1][1] = b4[3];
                ldsm4(b4, stb + (uint32_t)(3 * TILE_B + nloc * 80 + kb_ * 2));
                bl[nt2 * 2 + 0][0] = b4[0]; bl[nt2 * 2 + 0][1] = b4[1];
                bl[nt2 * 2 + 1][0] = b4[2]; bl[nt2 * 2 + 1][1] = b4[3];
            }
#pragma unroll
            for (int mt = 0; mt < 4; mt++) {
                uint32_t a4[4];
                int mloc = wm + mt * 16 + (g & 1) * 8 + r;
                int ka_ = k16 * 16 + (g >> 1) * 8;
                ldsm4(a4, stb + (uint32_t)(0 * TILE_B + mloc * 80 + ka_ * 2));
#pragma unroll
                for (int nt = 0; nt < 4; nt++) mma_bf16(acc[mt][nt], a4, bh[nt]);
#pragma unroll
                for (int nt = 0; nt < 4; nt++) mma_bf16(acc[mt][nt], a4, bl[nt]);
                ldsm4(a4, stb + (uint32_t)(1 * TILE_B + mloc * 80 + ka_ * 2));
#pragma unroll
                for (int nt = 0; nt < 4; nt++) mma_bf16(acc[mt][nt], a4, bh[nt]);
            }
        }
        __syncthreads();   // protect buffer i from next-iter overwrite
    }

    // ---- epilogue: register-direct ----
    float* outF = Cf;
    int Nout = N;
    int nbase = bn;
    const float* bb = bias;
    if (mode == 3) {
        int part = bn / 768;
        outF = Cf + (size_t)part * M * 768;
        nbase = bn - part * 768;
        Nout = 768;
        bb = (part == 0) ? bias : (part == 1) ? bias2 : bias3;
    } else if (mode == 4) {
        outF = Cf + (size_t)blockIdx.z * M * N;
    }

    const int r0 = lane >> 2, c0 = (lane & 3) * 2;
    float bv[4][2];
#pragma unroll
    for (int nt = 0; nt < 4; nt++) {
        int n = nbase + wn + nt * 8 + c0;
        bv[nt][0] = bb ? __ldg(bb + n) : 0.f;
        bv[nt][1] = bb ? __ldg(bb + n + 1) : 0.f;
    }

#pragma unroll
    for (int mt = 0; mt < 4; mt++) {
#pragma unroll
        for (int half = 0; half < 2; half++) {
            int m = bm + wm + mt * 16 + half * 8 + r0;
            if (m >= M) continue;
#pragma unroll
            for (int nt = 0; nt < 4; nt++) {
                int n = nbase + wn + nt * 8 + c0;
                float v0 = acc[mt][nt][half * 2 + 0] + bv[nt][0];
                float v1 = acc[mt][nt][half * 2 + 1] + bv[nt][1];
                if (mode == 1) {
                    v0 = 0.5f * v0 * (1.f + erff(v0 * 0.70710678118654752440f));
                    v1 = 0.5f * v1 * (1.f + erff(v1 * 0.70710678118654752440f));
                    __nv_bfloat16 h0 = __float2bfloat16(v0);
                    __nv_bfloat16 h1 = __float2bfloat16(v1);
                    __nv_bfloat162 hi; hi.x = h0; hi.y = h1;
                    __nv_bfloat162 lo;
                    lo.x = __float2bfloat16(v0 - __bfloat162float(h0));
                    lo.y = __float2bfloat16(v1 - __bfloat162float(h1));
                    *(__nv_bfloat162*)(Chi + (size_t)m * N + n) = hi;
                    *(__nv_bfloat162*)(Clo + (size_t)m * N + n) = lo;
                } else {
                    if (mode == 2) {
                        float2 rr = *(const float2*)(res + (size_t)m * N + n);
                        v0 += rr.x; v1 += rr.y;
                    }
                    float2 o; o.x = v0; o.y = v1;
                    *(float2*)(outF + (size_t)m * Nout + n) = o;
                }
            }
        }
    }
}

// ---------------- split-K combine (plain, last layer) ----------------
__global__ void combine_k(float* __restrict__ x, const float* __restrict__ p0,
                          const float* __restrict__ p1, const float* __restrict__ bias)
{
    int i = blockIdx.x * blockDim.x + threadIdx.x;
    if (i < NTOK * BD) {
        x[i] += p0[i] + p1[i] + bias[i % BD];
    }
}

// ---------------- weight prep: single launch for all weights ----------------
__device__ __forceinline__ void wsplit_tile(
    const float* __restrict__ s, __nv_bfloat16* __restrict__ oh, __nv_bfloat16* __restrict__ ol,
    int K, int N, int kb, int nb, float (*t)[33])
{
    const int tx = threadIdx.x & 31, ty = threadIdx.x >> 5;
#pragma unroll
    for (int r = 0; r < 4; r++) {
        int row = ty + (r << 3);
        t[row][tx] = s[(size_t)(kb + row) * N + nb + tx];
    }
    __syncthreads();
#pragma unroll
    for (int r = 0; r < 4; r++) {
        int row = ty + (r << 3);
        float v = t[tx][row];
        __nv_bfloat16 h = __float2bfloat16(v);
        size_t o = (size_t)(nb + row) * K + kb + tx;
        oh[o] = h;
        ol[o] = __float2bfloat16(v - __bfloat162float(h));
    }
}

#define WPREP_PER_L 6912    // 4*576 + 2*2304
#define WPREP_BLOCKS (NLAY * WPREP_PER_L + 576)

__global__ __launch_bounds__(256) void wprep_all(
    const float* __restrict__ Wq, const float* __restrict__ Wk,
    const float* __restrict__ Wv, const float* __restrict__ Wo,
    const float* __restrict__ Wf1, const float* __restrict__ Wf2,
    const float* __restrict__ pw,
    __nv_bfloat16* __restrict__ wh, __nv_bfloat16* __restrict__ wl,
    __nv_bfloat16* __restrict__ pwh, __nv_bfloat16* __restrict__ pwl)
{
    __shared__ float t[32][33];
    int bid = blockIdx.x;
    if (bid >= NLAY * WPREP_PER_L) {
        // patch_w: already [N=768, K=768] K-major; elementwise split
        int idx = bid - NLAY * WPREP_PER_L;
#pragma unroll
        for (int r = 0; r < 4; r++) {
            int i = idx * 1024 + r * 256 + threadIdx.x;
            float v = pw[i];
            __nv_bfloat16 h = __float2bfloat16(v);
            pwh[i] = h;
            pwl[i] = __float2bfloat16(v - __bfloat162float(h));
        }
        return;
    }
    int l = bid / WPREP_PER_L, r = bid % WPREP_PER_L;
    const float* src; size_t doff; int K, N, idx;
    if (r < 2304) {
        int g = r / 576; idx = r % 576;
        src = (g == 0 ? Wq : g == 1 ? Wk : g == 2 ? Wv : Wo) + (size_t)l * SZ_D2;
        doff = (size_t)g * SZ_D2; K = 768; N = 768;
    } else if (r < 4608) {
        idx = r - 2304; src = Wf1 + (size_t)l * SZ_DF; doff = OFF_F1; K = 768; N = 3072;
    } else {
        idx = r - 4608; src = Wf2 + (size_t)l * SZ_DF; doff = OFF_F2; K = 3072; N = 768;
    }
    int ntx = N / 32;
    int tx = idx % ntx, ty = idx / ntx;
    wsplit_tile(src, wh + (size_t)l * LW + doff, wl + (size_t)l * LW + doff,
                K, N, ty * 32, tx * 32, t);
}

// ---------------- layernorm ----------------
__device__ __forceinline__ float block_sum(float v, float* red)
{
#pragma unroll
    for (int o = 16; o; o >>= 1) v += __shfl_xor_sync(0xffffffffu, v, o);
    int w = threadIdx.x >> 5;
    if ((threadIdx.x & 31) == 0) red[w] = v;
    __syncthreads();
    float t = 0.f;
    if (threadIdx.x < 32) {
        t = (threadIdx.x < 8) ? red[threadIdx.x] : 0.f;
#pragma unroll
        for (int o = 4; o; o >>= 1) t += __shfl_xor_sync(0xffffffffu, t, o);
        if (threadIdx.x == 0) red[0] = t;
    }
    __syncthreads();
    float r = red[0];
    __syncthreads();
    return r;
}

__global__ __launch_bounds__(256) void ln_kernel(
    const float* __restrict__ X, const float* __restrict__ g,
    const float* __restrict__ bb, float* __restrict__ out, size_t in_stride)
{
    __shared__ float red[8];
    const int tid = threadIdx.x;
    const float* xr = X + (size_t)blockIdx.x * in_stride;
    float v0 = xr[tid], v1 = xr[tid + 256], v2 = xr[tid + 512];
    float s = block_sum(v0 + v1 + v2, red);
    float mean = s * (1.f / 768.f);
    float d0 = v0 - mean, d1 = v1 - mean, d2 = v2 - mean;
    float sq = block_sum(d0 * d0 + d1 * d1 + d2 * d2, red);
    float rstd = rsqrtf(sq * (1.f / 768.f) + 1e-5f);
    float* orow = out + (size_t)blockIdx.x * BD;
    orow[tid]       = d0 * rstd * g[tid]       + bb[tid];
    orow[tid + 256] = d1 * rstd * g[tid + 256] + bb[tid + 256];
    orow[tid + 512] = d2 * rstd * g[tid + 512] + bb[tid + 512];
}

__device__ __forceinline__ void ln_core_split(
    float v0, float v1, float v2, const float* g, const float* bb,
    __nv_bfloat16* oh, __nv_bfloat16* ol, size_t ro, int tid, float* red)
{
    float s = block_sum(v0 + v1 + v2, red);
    float mean = s * (1.f / 768.f);
    float d0 = v0 - mean, d1 = v1 - mean, d2 = v2 - mean;
    float sq = block_sum(d0 * d0 + d1 * d1 + d2 * d2, red);
    float rstd = rsqrtf(sq * (1.f / 768.f) + 1e-5f);
#pragma unroll
    for (int j = 0; j < 3; j++) {
        float d = (j == 0) ? d0 : (j == 1) ? d1 : d2;
        int c = tid + j * 256;
        float y = d * rstd * g[c] + bb[c];
        __nv_bfloat16 h = __float2bfloat16(y);
        oh[ro + c] = h;
        ol[ro + c] = __float2bfloat16(y - __bfloat162float(h));
    }
}

__global__ __launch_bounds__(256) void ln_split(
    const float* __restrict__ X, const float* __restrict__ g,
    const float* __restrict__ bb, __nv_bfloat16* __restrict__ oh,
    __nv_bfloat16* __restrict__ ol)
{
    __shared__ float red[8];
    const int tid = threadIdx.x;
    size_t ro = (size_t)blockIdx.x * BD;
    float v0 = X[ro + tid], v1 = X[ro + tid + 256], v2 = X[ro + tid + 512];
    ln_core_split(v0, v1, v2, g, bb, oh, ol, ro, tid, red);
}

// fused: x += p0 + p1 + bias_ff2; then LN(x) -> split bf16
__global__ __launch_bounds__(256) void combine_ln_split(
    float* __restrict__ x, const float* __restrict__ p0, const float* __restrict__ p1,
    const float* __restrict__ bf2v, const float* __restrict__ g,
    const float* __restrict__ bb, __nv_bfloat16* __restrict__ oh,
    __nv_bfloat16* __restrict__ ol)
{
    __shared__ float red[8];
    const int tid = threadIdx.x;
    size_t ro = (size_t)blockIdx.x * BD;
    float v0 = x[ro + tid]       + p0[ro + tid]       + p1[ro + tid]       + bf2v[tid];
    float v1 = x[ro + tid + 256] + p0[ro + tid + 256] + p1[ro + tid + 256] + bf2v[tid + 256];
    float v2 = x[ro + tid + 512] + p0[ro + tid + 512] + p1[ro + tid + 512] + bf2v[tid + 512];
    x[ro + tid] = v0; x[ro + tid + 256] = v1; x[ro + tid + 512] = v2;
    ln_core_split(v0, v1, v2, g, bb, oh, ol, ro, tid, red);
}

// ---------------- attention (query-tiled QT=4) ----------------
#define QT 4
#define ATTN_SMEM_FLOATS (SPAD * 65 + SPAD * 64)   // Ks + Vs2
#define ATTN_SMEM_BYTES  (ATTN_SMEM_FLOATS * 4)    // 103200 -> 2 CTAs/SM

__global__ __launch_bounds__(256) void attn_kernel(
    const float* __restrict__ Q, const float* __restrict__ K,
    const float* __restrict__ V, __nv_bfloat16* __restrict__ Oh,
    __nv_bfloat16* __restrict__ Ol)
{
    extern __shared__ float sm[];
    float* Ks = sm;                       // [SPAD][65]
    float2* Vs2 = (float2*)(sm + SPAD * 65);  // [SPAD][32]: (d, d+32) pairs

    const int bh = blockIdx.x;
    const int b = bh / NH, h = bh % NH;
    const size_t base = (size_t)b * SEQ * BD + (size_t)h * DH;
    const int tid = threadIdx.x;

    for (int i = tid; i < SPAD * 65; i += 256) {
        int s = i / 65, d = i - s * 65;
        float kv = 0.f;
        if (s < SEQ && d < DH) kv = K[base + (size_t)s * BD + d];
        Ks[i] = kv;
    }
    for (int i = tid; i < SPAD * 32; i += 256) {
        int s = i >> 5, l = i & 31;
        float2 vv = make_float2(0.f, 0.f);
        if (s < SEQ) {
            vv.x = V[base + (size_t)s * BD + l];
            vv.y = V[base + (size_t)s * BD + l + 32];
        }
        Vs2[i] = vv;
    }
    __syncthreads();

    const int warp = tid >> 5, lane = tid & 31;

    for (int sb = 0; sb < 7; sb++) {          // ceil(197/32) sweeps of 32 queries
        const int s0 = sb * 32 + warp * QT;

        // preload q rows into registers (clamped for invalid queries)
        float qreg[QT][2];
#pragma unroll
        for (int qi = 0; qi < QT; qi++) {
            int sc = min(s0 + qi, SEQ - 1);
            qreg[qi][0] = __ldg(Q + base + (size_t)sc * BD + lane);
            qreg[qi][1] = __ldg(Q + base + (size_t)sc * BD + lane + 32);
        }

        float acc[QT][7];
#pragma unroll
        for (int qi = 0; qi < QT; qi++)
#pragma unroll
            for (int j = 0; j < 7; j++) acc[qi][j] = 0.f;

#pragma unroll 8
        for (int d = 0; d < DH; d++) {
            const int srcl = d & 31;
            float qd[QT];
#pragma unroll
            for (int qi = 0; qi < QT; qi++)
                qd[qi] = __shfl_sync(0xffffffffu,
                                     (d < 32) ? qreg[qi][0] : qreg[qi][1], srcl);
#pragma unroll
            for (int j = 0; j < 7; j++) {
                int t = lane + j * 32;   // t<=223 stays inside dyn-smem alloc; masked below
                float kv = Ks[t * 65 + d];
#pragma unroll
                for (int qi = 0; qi < QT; qi++)
                    acc[qi][j] = fmaf(qd[qi], kv, acc[qi][j]);
            }
        }

        // softmax per query (exp values kept in acc, normalization folded at end)
        float inv[QT];
#pragma unroll
        for (int qi = 0; qi < QT; qi++) {
            float mx = -1e30f;
#pragma unroll
            for (int j = 0; j < 7; j++)
                if (lane + j * 32 < SEQ) mx = fmaxf(mx, acc[qi][j] * 0.125f);
#pragma unroll
            for (int o = 16; o; o >>= 1) mx = fmaxf(mx, __shfl_xor_sync(0xffffffffu, mx, o));
            float sum = 0.f;
#pragma unroll
            for (int j = 0; j < 7; j++) {
                int t = lane + j * 32;
                float e = (t < SEQ) ? __expf(acc[qi][j] * 0.125f - mx) : 0.f;
                acc[qi][j] = e;
                sum += e;
            }
#pragma unroll
            for (int o = 16; o; o >>= 1) sum += __shfl_xor_sync(0xffffffffu, sum, o);
            inv[qi] = 1.f / sum;
        }

        // PV: P broadcast from registers via shfl, V as float2
        float o[QT][2];
#pragma unroll
        for (int qi = 0; qi < QT; qi++) { o[qi][0] = 0.f; o[qi][1] = 0.f; }

#pragma unroll
        for (int j = 0; j < 7; j++) {
            const int tmax = (j < 6) ? 32 : (SEQ - 192);   // 5 on last group
            for (int sl = 0; sl < tmax; sl++) {
                float2 vv = Vs2[(j * 32 + sl) * 32 + lane];
#pragma unroll
                for (int qi = 0; qi < QT; qi++) {
                    float p = __shfl_sync(0xffffffffu, acc[qi][j], sl);
                    o[qi][0] = fmaf(p, vv.x, o[qi][0]);
                    o[qi][1] = fmaf(p, vv.y, o[qi][1]);
                }
            }
        }

#pragma unroll
        for (int qi = 0; qi < QT; qi++) {
            int s = s0 + qi;
            if (s < SEQ) {
                float v0 = o[qi][0] * inv[qi];
                float v1 = o[qi][1] * inv[qi];
                __nv_bfloat16 h0 = __float2bfloat16(v0);
                Oh[base + (size_t)s * BD + lane] = h0;
                Ol[base + (size_t)s * BD + lane] = __float2bfloat16(v0 - __bfloat162float(h0));
                __nv_bfloat16 h1 = __float2bfloat16(v1);
                Oh[base + (size_t)s * BD + lane + 32] = h1;
                Ol[base + (size_t)s * BD + lane + 32] = __float2bfloat16(v1 - __bfloat162float(h1));
            }
        }
    }
}

// ---------------- small kernels ----------------
__global__ void im2col_split(const float* __restrict__ X, __nv_bfloat16* __restrict__ ch,
                             __nv_bfloat16* __restrict__ cl)
{
    int idx = blockIdx.x * blockDim.x + threadIdx.x;
    if (idx >= NPATCH * BD) return;
    int m = idx / BD, kk = idx - m * BD;
    int b = m / 196, hw = m - b * 196;
    int ph = hw / 14, pw = hw - ph * 14;
    int c = kk >> 8, r = kk & 255, p = r >> 4, q = r & 15;
    float v = X[((size_t)(b * 3 + c) * 224 + ph * 16 + p) * 224 + pw * 16 + q];
    __nv_bfloat16 h = __float2bfloat16(v);
    ch[idx] = h;
    cl[idx] = __float2bfloat16(v - __bfloat162float(h));
}

__global__ void assemble_k(const float* __restrict__ patches, const float* __restrict__ cls,
                           const float* __restrict__ pos, float* __restrict__ x)
{
    int idx = blockIdx.x * blockDim.x + threadIdx.x;
    if (idx >= NTOK * BD) return;
    int d = idx % BD;
    int t = idx / BD;
    int b = t / SEQ, s = t - b * SEQ;
    float v = (s == 0) ? cls[d] : patches[((size_t)b * 196 + (s - 1)) * BD + d];
    x[idx] = v + pos[(size_t)s * BD + d];
}

__global__ __launch_bounds__(256) void head_kernel(
    const float* __restrict__ xc, const float* __restrict__ W,
    const float* __restrict__ bias, float* __restrict__ out)
{
    __shared__ float xs[BD];
    const int b = blockIdx.x;
    for (int i = threadIdx.x; i < BD; i += 256) xs[i] = xc[(size_t)b * BD + i];
    __syncthreads();

    const int n0 = threadIdx.x;
    float acc[4] = {0.f, 0.f, 0.f, 0.f};
    for (int k = 0; k < BD; k++) {
        float xv = xs[k];
#pragma unroll
        for (int j = 0; j < 4; j++) {
            int n = n0 + j * 256;
            if (n < NCLS) acc[j] += xv * W[(size_t)k * NCLS + n];
        }
    }
#pragma unroll
    for (int j = 0; j < 4; j++) {
        int n = n0 + j * 256;
        if (n < NCLS) out[(size_t)b * NCLS + n] = acc[j] + bias[n];
    }
}

// ---------------- launch ----------------
extern "C" void kernel_launch(void* const* d_in, const int* in_sizes, int n_in,
                              void* d_out, int out_size)
{
    const float* X       = (const float*)d_in[0];
    const float* patch_w = (const float*)d_in[1];
    const float* patch_b = (const float*)d_in[2];
    const float* cls_tok = (const float*)d_in[3];
    const float* pos_emb = (const float*)d_in[4];
    const float* ln1_g   = (const float*)d_in[5];
    const float* ln1_b   = (const float*)d_in[6];
    const float* Wq      = (const float*)d_in[7];
    const float* bq      = (const float*)d_in[8];
    const float* Wk      = (const float*)d_in[9];
    const float* bk      = (const float*)d_in[10];
    const float* Wv      = (const float*)d_in[11];
    const float* bv      = (const float*)d_in[12];
    const float* Wo      = (const float*)d_in[13];
    const float* bo      = (const float*)d_in[14];
    const float* ln2_g   = (const float*)d_in[15];
    const float* ln2_b   = (const float*)d_in[16];
    const float* Wf1     = (const float*)d_in[17];
    const float* bf1     = (const float*)d_in[18];
    const float* Wf2     = (const float*)d_in[19];
    const float* bf2     = (const float*)d_in[20];
    const float* lnf_g   = (const float*)d_in[21];
    const float* lnf_b   = (const float*)d_in[22];
    const float* head_w  = (const float*)d_in[23];
    const float* head_b  = (const float*)d_in[24];
    float* out = (float*)d_out;

    float *x, *h, *qkv, *cls;
    __nv_bfloat16 *hh, *hl, *ah, *al, *fh, *fl, *ch, *cl, *wh, *wl, *pwh, *pwl;
    cudaGetSymbolAddress((void**)&x,   g_x);
    cudaGetSymbolAddress((void**)&h,   g_h);
    cudaGetSymbolAddress((void**)&qkv, g_qkv);
    cudaGetSymbolAddress((void**)&cls, g_cls);
    cudaGetSymbolAddress((void**)&hh,  g_hh);
    cudaGetSymbolAddress((void**)&hl,  g_hl);
    cudaGetSymbolAddress((void**)&ah,  g_ah);
    cudaGetSymbolAddress((void**)&al,  g_al);
    cudaGetSymbolAddress((void**)&fh,  g_fh);
    cudaGetSymbolAddress((void**)&fl,  g_fl);
    cudaGetSymbolAddress((void**)&ch,  g_ch);
    cudaGetSymbolAddress((void**)&cl,  g_cl);
    cudaGetSymbolAddress((void**)&wh,  g_wh);
    cudaGetSymbolAddress((void**)&wl,  g_wl);
    cudaGetSymbolAddress((void**)&pwh, g_pwh);
    cudaGetSymbolAddress((void**)&pwl, g_pwl);

    cudaFuncSetAttribute(gemm_tc, cudaFuncAttributeMaxDynamicSharedMemorySize, GT_SMEM);
    cudaFuncSetAttribute(attn_kernel, cudaFuncAttributeMaxDynamicSharedMemorySize, ATTN_SMEM_BYTES);

    // [0] weight prep: one launch (also makes ncu -s5 land on gemm_tc QKV)
    wprep_all<<<WPREP_BLOCKS, 256>>>(Wq, Wk, Wv, Wo, Wf1, Wf2, patch_w, wh, wl, pwh, pwl);

    // [1..3] patch embed
    im2col_split<<<(NPATCH * BD + 255) / 256, 256>>>(X, ch, cl);
    gemm_tc<<<dim3(6, 49), 256, GT_SMEM>>>(ch, cl, pwh, pwl, patch_b, nullptr, nullptr, nullptr,
                                           h, nullptr, nullptr, NPATCH, BD, BD, BD, 0);
    assemble_k<<<(NTOK * BD + 255) / 256, 256>>>(h, cls_tok, pos_emb, x);

    const dim3 gQKV(18, 50);       // N=2304 merged
    const dim3 gD(6, 50);          // N=768
    const dim3 gF1(24, 50);        // N=3072
    const dim3 gF2(6, 50, 2);      // N=768, split-K=2

    float* qF = qkv;
    float* kF = qkv + (size_t)NTOK * BD;
    float* vF = qkv + (size_t)2 * NTOK * BD;

    for (int l = 0; l < NLAY; l++) {
        const __nv_bfloat16* wlh = wh + (size_t)l * LW;
        const __nv_bfloat16* wll = wl + (size_t)l * LW;

        // ln1 (fused with previous layer's FF2 combine for l>0)
        if (l == 0)
            ln_split<<<NTOK, 256>>>(x, ln1_g, ln1_b, hh, hl);
        else
            combine_ln_split<<<NTOK, 256>>>(x, qF, kF, bf2 + (l - 1) * BD,
                                            ln1_g + l * BD, ln1_b + l * BD, hh, hl);

        // merged QKV GEMM
        gemm_tc<<<gQKV, 256, GT_SMEM>>>(hh, hl, wlh + OFF_Q, wll + OFF_Q,
                                        bq + l * BD, bk + l * BD, bv + l * BD, nullptr,
                                        qkv, nullptr, nullptr, NTOK, 3 * BD, BD, BD, 3);

        attn_kernel<<<BATCH * NH, 256, ATTN_SMEM_BYTES>>>(qF, kF, vF, ah, al);

        gemm_tc<<<gD, 256, GT_SMEM>>>(ah, al, wlh + OFF_O, wll + OFF_O,
                                      bo + l * BD, nullptr, nullptr, x,
                                      x, nullptr, nullptr, NTOK, BD, BD, BD, 2);

        ln_split<<<NTOK, 256>>>(x, ln2_g + l * BD, ln2_b + l * BD, hh, hl);

        gemm_tc<<<gF1, 256, GT_SMEM>>>(hh, hl, wlh + OFF_F1, wll + OFF_F1,
                                       bf1 + l * FF, nullptr, nullptr, nullptr,
                                       nullptr, fh, fl, NTOK, FF, BD, BD, 1);

        // FF2 split-K=2: partials into qkv scratch, combined by next layer's fused LN
        gemm_tc<<<gF2, 256, GT_SMEM>>>(fh, fl, wlh + OFF_F2, wll + OFF_F2,
                                       nullptr, nullptr, nullptr, nullptr,
                                       qkv, nullptr, nullptr, NTOK, BD, FF / 2, FF, 4);
    }

    // last layer's FF2 combine, then final LN on cls rows + head
    combine_k<<<(NTOK * BD + 255) / 256, 256>>>(x, qF, kF, bf2 + 11 * BD);
    ln_kernel<<<BATCH, 256>>>(x, lnf_g, lnf_b, cls, (size_t)SEQ * BD);
    head_kernel<<<BATCH, 256>>>(cls, head_w, head_b, out);
}

// round 13
// speedup vs baseline: 3.7813x; 1.2806x over previous
#include <cuda_runtime.h>
#include <cuda_fp16.h>
#include <cstdint>
#include <cstddef>

// ---------------- problem constants ----------------
#define BATCH  32
#define SEQ    197
#define BD     768
#define NH     12
#define DH     64
#define NLAY   12
#define FF     3072
#define NCLS   1000
#define NTOK   (BATCH * SEQ)     // 6304
#define NPATCH (BATCH * 196)     // 6272
#define SPAD   200

#define SZ_D2  (768 * 768)
#define SZ_DF  (768 * 3072)
#define LW     ((size_t)(4 * SZ_D2) + (size_t)(2 * SZ_DF))
#define OFF_Q  ((size_t)0)
#define OFF_K  ((size_t)SZ_D2)
#define OFF_V  ((size_t)(2 * SZ_D2))
#define OFF_O  ((size_t)(3 * SZ_D2))
#define OFF_F1 ((size_t)(4 * SZ_D2))
#define OFF_F2 ((size_t)(4 * SZ_D2) + (size_t)SZ_DF)

// ---------------- device scratch (bss, no allocation) ----------------
__device__ __align__(128) float g_x[(size_t)NTOK * BD];
__device__ __align__(128) float g_h[(size_t)NTOK * BD];
__device__ __align__(128) float g_qkv[(size_t)3 * NTOK * BD];   // QKV out; FF2 split-K partials
__device__ __align__(128) float g_cls[(size_t)BATCH * BD];

__device__ __align__(128) __half g_hh[(size_t)NTOK * BD];
__device__ __align__(128) __half g_hl[(size_t)NTOK * BD];
__device__ __align__(128) __half g_ah[(size_t)NTOK * BD];
__device__ __align__(128) __half g_al[(size_t)NTOK * BD];
__device__ __align__(128) __half g_fh[(size_t)NTOK * FF];
__device__ __align__(128) __half g_fl[(size_t)NTOK * FF];
__device__ __align__(128) __half g_ch[(size_t)NPATCH * BD];
__device__ __align__(128) __half g_cl[(size_t)NPATCH * BD];
__device__ __align__(128) __half g_wh[(size_t)NLAY * LW];      // weights: single fp16 (hi only)
__device__ __align__(128) __half g_pwh[(size_t)SZ_D2];

// ---------------- PTX helpers (generic compute_103-safe) ----------------
__device__ __forceinline__ uint32_t smem_u32(const void* p) {
    uint32_t a;
    asm("{ .reg .u64 t; cvta.to.shared.u64 t, %1; cvt.u32.u64 %0, t; }" : "=r"(a) : "l"(p));
    return a;
}

__device__ __forceinline__ void cp16(uint32_t dst, const void* src) {
    asm volatile("cp.async.cg.shared.global [%0], [%1], 16;" :: "r"(dst), "l"(src) : "memory");
}
#define CP_COMMIT() asm volatile("cp.async.commit_group;" ::: "memory")
#define CP_WAIT1()  asm volatile("cp.async.wait_group 1;" ::: "memory")
#define CP_WAIT0()  asm volatile("cp.async.wait_group 0;" ::: "memory")

__device__ __forceinline__ void ldsm4(uint32_t* r, uint32_t addr) {
    asm volatile("ldmatrix.sync.aligned.m8n8.x4.shared.b16 {%0,%1,%2,%3}, [%4];"
        : "=r"(r[0]), "=r"(r[1]), "=r"(r[2]), "=r"(r[3]) : "r"(addr));
}

__device__ __forceinline__ void mma_f16(float* d, const uint32_t* a, const uint32_t* b) {
    asm volatile(
        "mma.sync.aligned.m16n8k16.row.col.f32.f16.f16.f32 "
        "{%0,%1,%2,%3}, {%4,%5,%6,%7}, {%8,%9}, {%0,%1,%2,%3};"
        : "+f"(d[0]), "+f"(d[1]), "+f"(d[2]), "+f"(d[3])
        : "r"(a[0]), "r"(a[1]), "r"(a[2]), "r"(a[3]), "r"(b[0]), "r"(b[1]));
}

__device__ __forceinline__ void split_h(float v, __half& h, __half& l) {
    h = __float2half_rn(v);
    l = __float2half_rn(v - __half2float(h));
}

// ---------------- tensor-core split-fp16 GEMM ----------------
// D[m,n] = sum_k A[m,k]*B[n,k], A = Ah+Al (fp16 split), B = Bh (fp16)
// 2-pass: Ah*Bh + Al*Bh   (dropped A*(B-Bh) ~ 2^-12)
// mode 0: Cf = D + bias
// mode 1: gelu(D + bias) -> (Chi, Clo) split fp16
// mode 2: Cf = D + bias + res
// mode 3: QKV partitioned epilogue
// mode 4: raw split-K partial: Cf + blockIdx.z*M*N = D (no bias)
#define TILE_B   10240               // 128 rows * 80B (32 fp16 + 8 pad)
#define STAGE3_B (3 * TILE_B)        // Ah, Al, Bh
#define GT_SMEM  (3 * STAGE3_B)      // 92160, 3-stage pipeline

__global__ __launch_bounds__(256, 2) void gemm_tc(
    const __half* __restrict__ Ahi, const __half* __restrict__ Alo,
    const __half* __restrict__ Bhi,
    const float* __restrict__ bias, const float* __restrict__ bias2,
    const float* __restrict__ bias3, const float* __restrict__ res,
    float* __restrict__ Cf, __half* __restrict__ Chi, __half* __restrict__ Clo,
    int M, int N, int Kloc, int Kstride, int mode)
{
    extern __shared__ __align__(128) char smem[];
    const uint32_t sb = smem_u32(smem);
    const int tid = threadIdx.x, wid = tid >> 5, lane = tid & 31;
    const int bm = blockIdx.y * 128, bn = blockIdx.x * 128;
    const int wm = (wid & 1) * 64, wn = (wid >> 1) * 32;
    const size_t kz = (size_t)blockIdx.z * (size_t)Kloc;

    float acc[4][4][4];
#pragma unroll
    for (int mt = 0; mt < 4; mt++)
#pragma unroll
        for (int nt = 0; nt < 4; nt++)
#pragma unroll
            for (int e = 0; e < 4; e++) acc[mt][nt][e] = 0.f;

    const __half* src[3] = {Ahi, Alo, Bhi};
    const int NKs = Kloc >> 5;

    auto load_stage = [&](int st, int k0) {
        uint32_t base = sb + (uint32_t)st * STAGE3_B;
        size_t kg = kz + (size_t)k0;
#pragma unroll
        for (int t = 0; t < 3; t++) {
#pragma unroll
            for (int j = 0; j < 2; j++) {
                int cid = tid + (j << 8);
                int row = cid >> 2, chk = cid & 3;
                int rg = (t < 2) ? min(bm + row, M - 1) : (bn + row);
                cp16(base + (uint32_t)(t * TILE_B + row * 80 + chk * 16),
                     src[t] + (size_t)rg * Kstride + kg + chk * 8);
            }
        }
        CP_COMMIT();
    };

    load_stage(0, 0);
    if (NKs > 1) load_stage(1, 32);

    for (int i = 0; i < NKs; i++) {
        if (i + 1 < NKs) CP_WAIT1(); else CP_WAIT0();
        __syncthreads();   // stage i visible to all; all warps done with stage (i-1)
        if (i + 2 < NKs) load_stage((i + 2) % 3, (i + 2) << 5);

        const uint32_t stb = sb + (uint32_t)(i % 3) * STAGE3_B;
        const int g = lane >> 3, r = lane & 7;

#pragma unroll
        for (int k16 = 0; k16 < 2; k16++) {
            uint32_t bh[4][2];
#pragma unroll
            for (int nt2 = 0; nt2 < 2; nt2++) {
                uint32_t b4[4];
                int nloc = wn + nt2 * 16 + (g >> 1) * 8 + r;
                int kb_ = k16 * 16 + (g & 1) * 8;
                ldsm4(b4, stb + (uint32_t)(2 * TILE_B + nloc * 80 + kb_ * 2));
                bh[nt2 * 2 + 0][0] = b4[0]; bh[nt2 * 2 + 0][1] = b4[1];
                bh[nt2 * 2 + 1][0] = b4[2]; bh[nt2 * 2 + 1][1] = b4[3];
            }
#pragma unroll
            for (int mt = 0; mt < 4; mt++) {
                uint32_t a4[4];
                int mloc = wm + mt * 16 + (g & 1) * 8 + r;
                int ka_ = k16 * 16 + (g >> 1) * 8;
                ldsm4(a4, stb + (uint32_t)(0 * TILE_B + mloc * 80 + ka_ * 2));
#pragma unroll
                for (int nt = 0; nt < 4; nt++) mma_f16(acc[mt][nt], a4, bh[nt]);
                ldsm4(a4, stb + (uint32_t)(1 * TILE_B + mloc * 80 + ka_ * 2));
#pragma unroll
                for (int nt = 0; nt < 4; nt++) mma_f16(acc[mt][nt], a4, bh[nt]);
            }
        }
        // no trailing barrier: next iteration's top barrier protects stage reuse
    }

    // ---- epilogue: register-direct ----
    float* outF = Cf;
    int Nout = N;
    int nbase = bn;
    const float* bb = bias;
    if (mode == 3) {
        int part = bn / 768;
        outF = Cf + (size_t)part * M * 768;
        nbase = bn - part * 768;
        Nout = 768;
        bb = (part == 0) ? bias : (part == 1) ? bias2 : bias3;
    } else if (mode == 4) {
        outF = Cf + (size_t)blockIdx.z * M * N;
    }

    const int r0 = lane >> 2, c0 = (lane & 3) * 2;
    float bv[4][2];
#pragma unroll
    for (int nt = 0; nt < 4; nt++) {
        int n = nbase + wn + nt * 8 + c0;
        bv[nt][0] = bb ? __ldg(bb + n) : 0.f;
        bv[nt][1] = bb ? __ldg(bb + n + 1) : 0.f;
    }

#pragma unroll
    for (int mt = 0; mt < 4; mt++) {
#pragma unroll
        for (int half_ = 0; half_ < 2; half_++) {
            int m = bm + wm + mt * 16 + half_ * 8 + r0;
            if (m >= M) continue;
#pragma unroll
            for (int nt = 0; nt < 4; nt++) {
                int n = nbase + wn + nt * 8 + c0;
                float v0 = acc[mt][nt][half_ * 2 + 0] + bv[nt][0];
                float v1 = acc[mt][nt][half_ * 2 + 1] + bv[nt][1];
                if (mode == 1) {
                    v0 = 0.5f * v0 * (1.f + erff(v0 * 0.70710678118654752440f));
                    v1 = 0.5f * v1 * (1.f + erff(v1 * 0.70710678118654752440f));
                    __half h0, l0, h1, l1;
                    split_h(v0, h0, l0);
                    split_h(v1, h1, l1);
                    __half2 hi2; hi2.x = h0; hi2.y = h1;
                    __half2 lo2; lo2.x = l0; lo2.y = l1;
                    *(__half2*)(Chi + (size_t)m * N + n) = hi2;
                    *(__half2*)(Clo + (size_t)m * N + n) = lo2;
                } else {
                    if (mode == 2) {
                        float2 rr = *(const float2*)(res + (size_t)m * N + n);
                        v0 += rr.x; v1 += rr.y;
                    }
                    float2 o; o.x = v0; o.y = v1;
                    *(float2*)(outF + (size_t)m * Nout + n) = o;
                }
            }
        }
    }
}

// ---------------- split-K combine (plain, last layer) ----------------
__global__ void combine_k(float* __restrict__ x, const float* __restrict__ p0,
                          const float* __restrict__ p1, const float* __restrict__ bias)
{
    int i = blockIdx.x * blockDim.x + threadIdx.x;
    if (i < NTOK * BD) {
        x[i] += p0[i] + p1[i] + bias[i % BD];
    }
}

// ---------------- weight prep: transpose W[K,N] fp32 -> fp16 [N,K], one launch ----------------
__device__ __forceinline__ void wsplit_tile(
    const float* __restrict__ s, __half* __restrict__ oh,
    int K, int N, int kb, int nb, float (*t)[33])
{
    const int tx = threadIdx.x & 31, ty = threadIdx.x >> 5;
#pragma unroll
    for (int r = 0; r < 4; r++) {
        int row = ty + (r << 3);
        t[row][tx] = s[(size_t)(kb + row) * N + nb + tx];
    }
    __syncthreads();
#pragma unroll
    for (int r = 0; r < 4; r++) {
        int row = ty + (r << 3);
        oh[(size_t)(nb + row) * K + kb + tx] = __float2half_rn(t[tx][row]);
    }
}

#define WPREP_PER_L 6912    // 4*576 + 2*2304
#define WPREP_BLOCKS (NLAY * WPREP_PER_L + 576)

__global__ __launch_bounds__(256) void wprep_all(
    const float* __restrict__ Wq, const float* __restrict__ Wk,
    const float* __restrict__ Wv, const float* __restrict__ Wo,
    const float* __restrict__ Wf1, const float* __restrict__ Wf2,
    const float* __restrict__ pw,
    __half* __restrict__ wh, __half* __restrict__ pwh)
{
    __shared__ float t[32][33];
    int bid = blockIdx.x;
    if (bid >= NLAY * WPREP_PER_L) {
        // patch_w: already [N=768, K=768] K-major; elementwise convert
        int idx = bid - NLAY * WPREP_PER_L;
#pragma unroll
        for (int r = 0; r < 4; r++) {
            int i = idx * 1024 + r * 256 + threadIdx.x;
            pwh[i] = __float2half_rn(pw[i]);
        }
        return;
    }
    int l = bid / WPREP_PER_L, r = bid % WPREP_PER_L;
    const float* src; size_t doff; int K, N, idx;
    if (r < 2304) {
        int g = r / 576; idx = r % 576;
        src = (g == 0 ? Wq : g == 1 ? Wk : g == 2 ? Wv : Wo) + (size_t)l * SZ_D2;
        doff = (size_t)g * SZ_D2; K = 768; N = 768;
    } else if (r < 4608) {
        idx = r - 2304; src = Wf1 + (size_t)l * SZ_DF; doff = OFF_F1; K = 768; N = 3072;
    } else {
        idx = r - 4608; src = Wf2 + (size_t)l * SZ_DF; doff = OFF_F2; K = 3072; N = 768;
    }
    int ntx = N / 32;
    int tx = idx % ntx, ty = idx / ntx;
    wsplit_tile(src, wh + (size_t)l * LW + doff, K, N, ty * 32, tx * 32, t);
}

// ---------------- layernorm ----------------
__device__ __forceinline__ float block_sum(float v, float* red)
{
#pragma unroll
    for (int o = 16; o; o >>= 1) v += __shfl_xor_sync(0xffffffffu, v, o);
    int w = threadIdx.x >> 5;
    if ((threadIdx.x & 31) == 0) red[w] = v;
    __syncthreads();
    float t = 0.f;
    if (threadIdx.x < 32) {
        t = (threadIdx.x < 8) ? red[threadIdx.x] : 0.f;
#pragma unroll
        for (int o = 4; o; o >>= 1) t += __shfl_xor_sync(0xffffffffu, t, o);
        if (threadIdx.x == 0) red[0] = t;
    }
    __syncthreads();
    float r = red[0];
    __syncthreads();
    return r;
}

__global__ __launch_bounds__(256) void ln_kernel(
    const float* __restrict__ X, const float* __restrict__ g,
    const float* __restrict__ bb, float* __restrict__ out, size_t in_stride)
{
    __shared__ float red[8];
    const int tid = threadIdx.x;
    const float* xr = X + (size_t)blockIdx.x * in_stride;
    float v0 = xr[tid], v1 = xr[tid + 256], v2 = xr[tid + 512];
    float s = block_sum(v0 + v1 + v2, red);
    float mean = s * (1.f / 768.f);
    float d0 = v0 - mean, d1 = v1 - mean, d2 = v2 - mean;
    float sq = block_sum(d0 * d0 + d1 * d1 + d2 * d2, red);
    float rstd = rsqrtf(sq * (1.f / 768.f) + 1e-5f);
    float* orow = out + (size_t)blockIdx.x * BD;
    orow[tid]       = d0 * rstd * g[tid]       + bb[tid];
    orow[tid + 256] = d1 * rstd * g[tid + 256] + bb[tid + 256];
    orow[tid + 512] = d2 * rstd * g[tid + 512] + bb[tid + 512];
}

__device__ __forceinline__ void ln_core_split(
    float v0, float v1, float v2, const float* g, const float* bb,
    __half* oh, __half* ol, size_t ro, int tid, float* red)
{
    float s = block_sum(v0 + v1 + v2, red);
    float mean = s * (1.f / 768.f);
    float d0 = v0 - mean, d1 = v1 - mean, d2 = v2 - mean;
    float sq = block_sum(d0 * d0 + d1 * d1 + d2 * d2, red);
    float rstd = rsqrtf(sq * (1.f / 768.f) + 1e-5f);
#pragma unroll
    for (int j = 0; j < 3; j++) {
        float d = (j == 0) ? d0 : (j == 1) ? d1 : d2;
        int c = tid + j * 256;
        float y = d * rstd * g[c] + bb[c];
        __half h, l;
        split_h(y, h, l);
        oh[ro + c] = h;
        ol[ro + c] = l;
    }
}

__global__ __launch_bounds__(256) void ln_split(
    const float* __restrict__ X, const float* __restrict__ g,
    const float* __restrict__ bb, __half* __restrict__ oh, __half* __restrict__ ol)
{
    __shared__ float red[8];
    const int tid = threadIdx.x;
    size_t ro = (size_t)blockIdx.x * BD;
    float v0 = X[ro + tid], v1 = X[ro + tid + 256], v2 = X[ro + tid + 512];
    ln_core_split(v0, v1, v2, g, bb, oh, ol, ro, tid, red);
}

// fused: x += p0 + p1 + bias_ff2; then LN(x) -> split fp16
__global__ __launch_bounds__(256) void combine_ln_split(
    float* __restrict__ x, const float* __restrict__ p0, const float* __restrict__ p1,
    const float* __restrict__ bf2v, const float* __restrict__ g,
    const float* __restrict__ bb, __half* __restrict__ oh, __half* __restrict__ ol)
{
    __shared__ float red[8];
    const int tid = threadIdx.x;
    size_t ro = (size_t)blockIdx.x * BD;
    float v0 = x[ro + tid]       + p0[ro + tid]       + p1[ro + tid]       + bf2v[tid];
    float v1 = x[ro + tid + 256] + p0[ro + tid + 256] + p1[ro + tid + 256] + bf2v[tid + 256];
    float v2 = x[ro + tid + 512] + p0[ro + tid + 512] + p1[ro + tid + 512] + bf2v[tid + 512];
    x[ro + tid] = v0; x[ro + tid + 256] = v1; x[ro + tid + 512] = v2;
    ln_core_split(v0, v1, v2, g, bb, oh, ol, ro, tid, red);
}

// ---------------- attention (query-tiled QT=4) ----------------
#define QT 4
#define ATTN_SMEM_FLOATS (SPAD * 65 + SPAD * 64)   // Ks + Vs2
#define ATTN_SMEM_BYTES  (ATTN_SMEM_FLOATS * 4)    // 103200 -> 2 CTAs/SM

__global__ __launch_bounds__(256) void attn_kernel(
    const float* __restrict__ Q, const float* __restrict__ K,
    const float* __restrict__ V, __half* __restrict__ Oh, __half* __restrict__ Ol)
{
    extern __shared__ float sm[];
    float* Ks = sm;                           // [SPAD][65]
    float2* Vs2 = (float2*)(sm + SPAD * 65);  // [SPAD][32]: (d, d+32) pairs

    const int bh = blockIdx.x;
    const int b = bh / NH, h = bh % NH;
    const size_t base = (size_t)b * SEQ * BD + (size_t)h * DH;
    const int tid = threadIdx.x;

    for (int i = tid; i < SPAD * 65; i += 256) {
        int s = i / 65, d = i - s * 65;
        float kv = 0.f;
        if (s < SEQ && d < DH) kv = K[base + (size_t)s * BD + d];
        Ks[i] = kv;
    }
    for (int i = tid; i < SPAD * 32; i += 256) {
        int s = i >> 5, l = i & 31;
        float2 vv = make_float2(0.f, 0.f);
        if (s < SEQ) {
            vv.x = V[base + (size_t)s * BD + l];
            vv.y = V[base + (size_t)s * BD + l + 32];
        }
        Vs2[i] = vv;
    }
    __syncthreads();

    const int warp = tid >> 5, lane = tid & 31;

    for (int sb = 0; sb < 7; sb++) {
        const int s0 = sb * 32 + warp * QT;

        float qreg[QT][2];
#pragma unroll
        for (int qi = 0; qi < QT; qi++) {
            int sc = min(s0 + qi, SEQ - 1);
            qreg[qi][0] = __ldg(Q + base + (size_t)sc * BD + lane);
            qreg[qi][1] = __ldg(Q + base + (size_t)sc * BD + lane + 32);
        }

        float acc[QT][7];
#pragma unroll
        for (int qi = 0; qi < QT; qi++)
#pragma unroll
            for (int j = 0; j < 7; j++) acc[qi][j] = 0.f;

#pragma unroll 8
        for (int d = 0; d < DH; d++) {
            const int srcl = d & 31;
            float qd[QT];
#pragma unroll
            for (int qi = 0; qi < QT; qi++)
                qd[qi] = __shfl_sync(0xffffffffu,
                                     (d < 32) ? qreg[qi][0] : qreg[qi][1], srcl);
#pragma unroll
            for (int j = 0; j < 7; j++) {
                int t = lane + j * 32;
                float kv = Ks[t * 65 + d];
#pragma unroll
                for (int qi = 0; qi < QT; qi++)
                    acc[qi][j] = fmaf(qd[qi], kv, acc[qi][j]);
            }
        }

        float inv[QT];
#pragma unroll
        for (int qi = 0; qi < QT; qi++) {
            float mx = -1e30f;
#pragma unroll
            for (int j = 0; j < 7; j++)
                if (lane + j * 32 < SEQ) mx = fmaxf(mx, acc[qi][j] * 0.125f);
#pragma unroll
            for (int o = 16; o; o >>= 1) mx = fmaxf(mx, __shfl_xor_sync(0xffffffffu, mx, o));
            float sum = 0.f;
#pragma unroll
            for (int j = 0; j < 7; j++) {
                int t = lane + j * 32;
                float e = (t < SEQ) ? __expf(acc[qi][j] * 0.125f - mx) : 0.f;
                acc[qi][j] = e;
                sum += e;
            }
#pragma unroll
            for (int o = 16; o; o >>= 1) sum += __shfl_xor_sync(0xffffffffu, sum, o);
            inv[qi] = 1.f / sum;
        }

        float o[QT][2];
#pragma unroll
        for (int qi = 0; qi < QT; qi++) { o[qi][0] = 0.f; o[qi][1] = 0.f; }

#pragma unroll
        for (int j = 0; j < 7; j++) {
            const int tmax = (j < 6) ? 32 : (SEQ - 192);
            for (int sl = 0; sl < tmax; sl++) {
                float2 vv = Vs2[(j * 32 + sl) * 32 + lane];
#pragma unroll
                for (int qi = 0; qi < QT; qi++) {
                    float p = __shfl_sync(0xffffffffu, acc[qi][j], sl);
                    o[qi][0] = fmaf(p, vv.x, o[qi][0]);
                    o[qi][1] = fmaf(p, vv.y, o[qi][1]);
                }
            }
        }

#pragma unroll
        for (int qi = 0; qi < QT; qi++) {
            int s = s0 + qi;
            if (s < SEQ) {
                float v0 = o[qi][0] * inv[qi];
                float v1 = o[qi][1] * inv[qi];
                __half h0, l0, h1, l1;
                split_h(v0, h0, l0);
                split_h(v1, h1, l1);
                Oh[base + (size_t)s * BD + lane] = h0;
                Ol[base + (size_t)s * BD + lane] = l0;
                Oh[base + (size_t)s * BD + lane + 32] = h1;
                Ol[base + (size_t)s * BD + lane + 32] = l1;
            }
        }
    }
}

// ---------------- small kernels ----------------
__global__ void im2col_split(const float* __restrict__ X, __half* __restrict__ ch,
                             __half* __restrict__ cl)
{
    int idx = blockIdx.x * blockDim.x + threadIdx.x;
    if (idx >= NPATCH * BD) return;
    int m = idx / BD, kk = idx - m * BD;
    int b = m / 196, hw = m - b * 196;
    int ph = hw / 14, pw = hw - ph * 14;
    int c = kk >> 8, r = kk & 255, p = r >> 4, q = r & 15;
    float v = X[((size_t)(b * 3 + c) * 224 + ph * 16 + p) * 224 + pw * 16 + q];
    __half h, l;
    split_h(v, h, l);
    ch[idx] = h;
    cl[idx] = l;
}

__global__ void assemble_k(const float* __restrict__ patches, const float* __restrict__ cls,
                           const float* __restrict__ pos, float* __restrict__ x)
{
    int idx = blockIdx.x * blockDim.x + threadIdx.x;
    if (idx >= NTOK * BD) return;
    int d = idx % BD;
    int t = idx / BD;
    int b = t / SEQ, s = t - b * SEQ;
    float v = (s == 0) ? cls[d] : patches[((size_t)b * 196 + (s - 1)) * BD + d];
    x[idx] = v + pos[(size_t)s * BD + d];
}

__global__ __launch_bounds__(256) void head_kernel(
    const float* __restrict__ xc, const float* __restrict__ W,
    const float* __restrict__ bias, float* __restrict__ out)
{
    __shared__ float xs[BD];
    const int b = blockIdx.x;
    for (int i = threadIdx.x; i < BD; i += 256) xs[i] = xc[(size_t)b * BD + i];
    __syncthreads();

    const int n0 = threadIdx.x;
    float acc[4] = {0.f, 0.f, 0.f, 0.f};
    for (int k = 0; k < BD; k++) {
        float xv = xs[k];
#pragma unroll
        for (int j = 0; j < 4; j++) {
            int n = n0 + j * 256;
            if (n < NCLS) acc[j] += xv * W[(size_t)k * NCLS + n];
        }
    }
#pragma unroll
    for (int j = 0; j < 4; j++) {
        int n = n0 + j * 256;
        if (n < NCLS) out[(size_t)b * NCLS + n] = acc[j] + bias[n];
    }
}

// ---------------- launch ----------------
extern "C" void kernel_launch(void* const* d_in, const int* in_sizes, int n_in,
                              void* d_out, int out_size)
{
    const float* X       = (const float*)d_in[0];
    const float* patch_w = (const float*)d_in[1];
    const float* patch_b = (const float*)d_in[2];
    const float* cls_tok = (const float*)d_in[3];
    const float* pos_emb = (const float*)d_in[4];
    const float* ln1_g   = (const float*)d_in[5];
    const float* ln1_b   = (const float*)d_in[6];
    const float* Wq      = (const float*)d_in[7];
    const float* bq      = (const float*)d_in[8];
    const float* Wk      = (const float*)d_in[9];
    const float* bk      = (const float*)d_in[10];
    const float* Wv      = (const float*)d_in[11];
    const float* bv      = (const float*)d_in[12];
    const float* Wo      = (const float*)d_in[13];
    const float* bo      = (const float*)d_in[14];
    const float* ln2_g   = (const float*)d_in[15];
    const float* ln2_b   = (const float*)d_in[16];
    const float* Wf1     = (const float*)d_in[17];
    const float* bf1     = (const float*)d_in[18];
    const float* Wf2     = (const float*)d_in[19];
    const float* bf2     = (const float*)d_in[20];
    const float* lnf_g   = (const float*)d_in[21];
    const float* lnf_b   = (const float*)d_in[22];
    const float* head_w  = (const float*)d_in[23];
    const float* head_b  = (const float*)d_in[24];
    float* out = (float*)d_out;

    float *x, *h, *qkv, *cls;
    __half *hh, *hl, *ah, *al, *fh, *fl, *ch, *cl, *wh, *pwh;
    cudaGetSymbolAddress((void**)&x,   g_x);
    cudaGetSymbolAddress((void**)&h,   g_h);
    cudaGetSymbolAddress((void**)&qkv, g_qkv);
    cudaGetSymbolAddress((void**)&cls, g_cls);
    cudaGetSymbolAddress((void**)&hh,  g_hh);
    cudaGetSymbolAddress((void**)&hl,  g_hl);
    cudaGetSymbolAddress((void**)&ah,  g_ah);
    cudaGetSymbolAddress((void**)&al,  g_al);
    cudaGetSymbolAddress((void**)&fh,  g_fh);
    cudaGetSymbolAddress((void**)&fl,  g_fl);
    cudaGetSymbolAddress((void**)&ch,  g_ch);
    cudaGetSymbolAddress((void**)&cl,  g_cl);
    cudaGetSymbolAddress((void**)&wh,  g_wh);
    cudaGetSymbolAddress((void**)&pwh, g_pwh);

    cudaFuncSetAttribute(gemm_tc, cudaFuncAttributeMaxDynamicSharedMemorySize, GT_SMEM);
    cudaFuncSetAttribute(attn_kernel, cudaFuncAttributeMaxDynamicSharedMemorySize, ATTN_SMEM_BYTES);

    // [0] weight prep: one launch
    wprep_all<<<WPREP_BLOCKS, 256>>>(Wq, Wk, Wv, Wo, Wf1, Wf2, patch_w, wh, pwh);

    // patch embed
    im2col_split<<<(NPATCH * BD + 255) / 256, 256>>>(X, ch, cl);
    gemm_tc<<<dim3(6, 49), 256, GT_SMEM>>>(ch, cl, pwh, patch_b, nullptr, nullptr, nullptr,
                                           h, nullptr, nullptr, NPATCH, BD, BD, BD, 0);
    assemble_k<<<(NTOK * BD + 255) / 256, 256>>>(h, cls_tok, pos_emb, x);

    const dim3 gQKV(18, 50);       // N=2304 merged
    const dim3 gD(6, 50);          // N=768
    const dim3 gF1(24, 50);        // N=3072
    const dim3 gF2(6, 50, 2);      // N=768, split-K=2

    float* qF = qkv;
    float* kF = qkv + (size_t)NTOK * BD;
    float* vF = qkv + (size_t)2 * NTOK * BD;

    for (int l = 0; l < NLAY; l++) {
        const __half* wlh = wh + (size_t)l * LW;

        if (l == 0)
            ln_split<<<NTOK, 256>>>(x, ln1_g, ln1_b, hh, hl);
        else
            combine_ln_split<<<NTOK, 256>>>(x, qF, kF, bf2 + (l - 1) * BD,
                                            ln1_g + l * BD, ln1_b + l * BD, hh, hl);

        gemm_tc<<<gQKV, 256, GT_SMEM>>>(hh, hl, wlh + OFF_Q,
                                        bq + l * BD, bk + l * BD, bv + l * BD, nullptr,
                                        qkv, nullptr, nullptr, NTOK, 3 * BD, BD, BD, 3);

        attn_kernel<<<BATCH * NH, 256, ATTN_SMEM_BYTES>>>(qF, kF, vF, ah, al);

        gemm_tc<<<gD, 256, GT_SMEM>>>(ah, al, wlh + OFF_O,
                                      bo + l * BD, nullptr, nullptr, x,
                                      x, nullptr, nullptr, NTOK, BD, BD, BD, 2);

        ln_split<<<NTOK, 256>>>(x, ln2_g + l * BD, ln2_b + l * BD, hh, hl);

        gemm_tc<<<gF1, 256, GT_SMEM>>>(hh, hl, wlh + OFF_F1,
                                       bf1 + l * FF, nullptr, nullptr, nullptr,
                                       nullptr, fh, fl, NTOK, FF, BD, BD, 1);

        gemm_tc<<<gF2, 256, GT_SMEM>>>(fh, fl, wlh + OFF_F2,
                                       nullptr, nullptr, nullptr, nullptr,
                                       qkv, nullptr, nullptr, NTOK, BD, FF / 2, FF, 4);
    }

    combine_k<<<(NTOK * BD + 255) / 256, 256>>>(x, qF, kF, bf2 + 11 * BD);
    ln_kernel<<<BATCH, 256>>>(x, lnf_g, lnf_b, cls, (size_t)SEQ * BD);
    head_kernel<<<BATCH, 256>>>(cls, head_w, head_b, out);
}

// round 14
// speedup vs baseline: 4.5717x; 1.2090x over previous
#include <cuda_runtime.h>
#include <cuda_fp16.h>
#include <cstdint>
#include <cstddef>

// ---------------- problem constants ----------------
#define BATCH  32
#define SEQ    197
#define BD     768
#define NH     12
#define DH     64
#define NLAY   12
#define FF     3072
#define NCLS   1000
#define NTOK   (BATCH * SEQ)     // 6304
#define NPATCH (BATCH * 196)     // 6272

#define SZ_D2  (768 * 768)
#define SZ_DF  (768 * 3072)
#define LW     ((size_t)(4 * SZ_D2) + (size_t)(2 * SZ_DF))
#define OFF_Q  ((size_t)0)
#define OFF_K  ((size_t)SZ_D2)
#define OFF_V  ((size_t)(2 * SZ_D2))
#define OFF_O  ((size_t)(3 * SZ_D2))
#define OFF_F1 ((size_t)(4 * SZ_D2))
#define OFF_F2 ((size_t)(4 * SZ_D2) + (size_t)SZ_DF)

// ---------------- device scratch (bss, no allocation) ----------------
__device__ __align__(128) float g_x[(size_t)NTOK * BD];
__device__ __align__(128) float g_h[(size_t)NTOK * BD];
__device__ __align__(128) float g_pp[(size_t)2 * NTOK * BD];    // FF2 split-K partials
__device__ __align__(128) float g_cls[(size_t)BATCH * BD];

__device__ __align__(128) __half g_qkvh[(size_t)3 * NTOK * BD]; // QKV hi (parts Q,K,V)
__device__ __align__(128) __half g_qkvl[(size_t)3 * NTOK * BD]; // QKV lo
__device__ __align__(128) __half g_hh[(size_t)NTOK * BD];
__device__ __align__(128) __half g_hl[(size_t)NTOK * BD];
__device__ __align__(128) __half g_ah[(size_t)NTOK * BD];
__device__ __align__(128) __half g_al[(size_t)NTOK * BD];
__device__ __align__(128) __half g_fh[(size_t)NTOK * FF];
__device__ __align__(128) __half g_fl[(size_t)NTOK * FF];
__device__ __align__(128) __half g_ch[(size_t)NPATCH * BD];
__device__ __align__(128) __half g_cl[(size_t)NPATCH * BD];
__device__ __align__(128) __half g_wh[(size_t)NLAY * LW];
__device__ __align__(128) __half g_pwh[(size_t)SZ_D2];

// ---------------- PTX helpers (generic compute_103-safe) ----------------
__device__ __forceinline__ uint32_t smem_u32(const void* p) {
    uint32_t a;
    asm("{ .reg .u64 t; cvta.to.shared.u64 t, %1; cvt.u32.u64 %0, t; }" : "=r"(a) : "l"(p));
    return a;
}

__device__ __forceinline__ void cp16(uint32_t dst, const void* src) {
    asm volatile("cp.async.cg.shared.global [%0], [%1], 16;" :: "r"(dst), "l"(src) : "memory");
}
#define CP_COMMIT() asm volatile("cp.async.commit_group;" ::: "memory")
#define CP_WAIT0()  asm volatile("cp.async.wait_group 0;" ::: "memory")
#define CP_WAIT1()  asm volatile("cp.async.wait_group 1;" ::: "memory")
#define CP_WAIT2()  asm volatile("cp.async.wait_group 2;" ::: "memory")

__device__ __forceinline__ void ldsm4(uint32_t* r, uint32_t addr) {
    asm volatile("ldmatrix.sync.aligned.m8n8.x4.shared.b16 {%0,%1,%2,%3}, [%4];"
        : "=r"(r[0]), "=r"(r[1]), "=r"(r[2]), "=r"(r[3]) : "r"(addr));
}
__device__ __forceinline__ void ldsm4t(uint32_t* r, uint32_t addr) {
    asm volatile("ldmatrix.sync.aligned.m8n8.x4.trans.shared.b16 {%0,%1,%2,%3}, [%4];"
        : "=r"(r[0]), "=r"(r[1]), "=r"(r[2]), "=r"(r[3]) : "r"(addr));
}

__device__ __forceinline__ void mma_f16(float* d, const uint32_t* a, const uint32_t* b) {
    asm volatile(
        "mma.sync.aligned.m16n8k16.row.col.f32.f16.f16.f32 "
        "{%0,%1,%2,%3}, {%4,%5,%6,%7}, {%8,%9}, {%0,%1,%2,%3};"
        : "+f"(d[0]), "+f"(d[1]), "+f"(d[2]), "+f"(d[3])
        : "r"(a[0]), "r"(a[1]), "r"(a[2]), "r"(a[3]), "r"(b[0]), "r"(b[1]));
}

__device__ __forceinline__ void split_h(float v, __half& h, __half& l) {
    h = __float2half_rn(v);
    l = __float2half_rn(v - __half2float(h));
}
__device__ __forceinline__ uint32_t pack_split(float x, float y, uint32_t& lo) {
    __half hx, lx, hy, ly;
    split_h(x, hx, lx);
    split_h(y, hy, ly);
    __half2 hi2; hi2.x = hx; hi2.y = hy;
    __half2 lo2; lo2.x = lx; lo2.y = ly;
    lo = *(uint32_t*)&lo2;
    return *(uint32_t*)&hi2;
}

// ---------------- tensor-core split-fp16 GEMM ----------------
// D[m,n] = sum_k A[m,k]*B[n,k], A = Ah+Al (fp16 split), B = Bh (fp16)
// 2-pass: Ah*Bh + Al*Bh
// mode 0: Cf = D + bias
// mode 1: gelu(D + bias) -> (Chi, Clo) split fp16
// mode 2: Cf = D + bias + res
// mode 3: QKV partitioned -> (Chi, Clo) split fp16, per-part stride 768
// mode 4: raw split-K partial: Cf + blockIdx.z*M*N = D (no bias)
#define TILE_B   10240               // 128 rows * 80B (32 fp16 + 8 pad)
#define STAGE3_B (3 * TILE_B)        // Ah, Al, Bh
#define GT_SMEM  (3 * STAGE3_B)      // 92160, 3-stage pipeline

__global__ __launch_bounds__(256, 2) void gemm_tc(
    const __half* __restrict__ Ahi, const __half* __restrict__ Alo,
    const __half* __restrict__ Bhi,
    const float* __restrict__ bias, const float* __restrict__ bias2,
    const float* __restrict__ bias3, const float* __restrict__ res,
    float* __restrict__ Cf, __half* __restrict__ Chi, __half* __restrict__ Clo,
    int M, int N, int Kloc, int Kstride, int mode)
{
    extern __shared__ __align__(128) char smem[];
    const uint32_t sb = smem_u32(smem);
    const int tid = threadIdx.x, wid = tid >> 5, lane = tid & 31;
    const int bm = blockIdx.y * 128, bn = blockIdx.x * 128;
    const int wm = (wid & 1) * 64, wn = (wid >> 1) * 32;
    const size_t kz = (size_t)blockIdx.z * (size_t)Kloc;

    float acc[4][4][4];
#pragma unroll
    for (int mt = 0; mt < 4; mt++)
#pragma unroll
        for (int nt = 0; nt < 4; nt++)
#pragma unroll
            for (int e = 0; e < 4; e++) acc[mt][nt][e] = 0.f;

    const __half* src[3] = {Ahi, Alo, Bhi};
    const int NKs = Kloc >> 5;

    auto load_stage = [&](int st, int k0) {
        uint32_t base = sb + (uint32_t)st * STAGE3_B;
        size_t kg = kz + (size_t)k0;
#pragma unroll
        for (int t = 0; t < 3; t++) {
#pragma unroll
            for (int j = 0; j < 2; j++) {
                int cid = tid + (j << 8);
                int row = cid >> 2, chk = cid & 3;
                int rg = (t < 2) ? min(bm + row, M - 1) : (bn + row);
                cp16(base + (uint32_t)(t * TILE_B + row * 80 + chk * 16),
                     src[t] + (size_t)rg * Kstride + kg + chk * 8);
            }
        }
        CP_COMMIT();
    };

    load_stage(0, 0);
    if (NKs > 1) load_stage(1, 32);

    for (int i = 0; i < NKs; i++) {
        if (i + 1 < NKs) CP_WAIT1(); else CP_WAIT0();
        __syncthreads();
        if (i + 2 < NKs) load_stage((i + 2) % 3, (i + 2) << 5);

        const uint32_t stb = sb + (uint32_t)(i % 3) * STAGE3_B;
        const int g = lane >> 3, r = lane & 7;

#pragma unroll
        for (int k16 = 0; k16 < 2; k16++) {
            uint32_t bh[4][2];
#pragma unroll
            for (int nt2 = 0; nt2 < 2; nt2++) {
                uint32_t b4[4];
                int nloc = wn + nt2 * 16 + (g >> 1) * 8 + r;
                int kb_ = k16 * 16 + (g & 1) * 8;
                ldsm4(b4, stb + (uint32_t)(2 * TILE_B + nloc * 80 + kb_ * 2));
                bh[nt2 * 2 + 0][0] = b4[0]; bh[nt2 * 2 + 0][1] = b4[1];
                bh[nt2 * 2 + 1][0] = b4[2]; bh[nt2 * 2 + 1][1] = b4[3];
            }
#pragma unroll
            for (int mt = 0; mt < 4; mt++) {
                uint32_t a4[4];
                int mloc = wm + mt * 16 + (g & 1) * 8 + r;
                int ka_ = k16 * 16 + (g >> 1) * 8;
                ldsm4(a4, stb + (uint32_t)(0 * TILE_B + mloc * 80 + ka_ * 2));
#pragma unroll
                for (int nt = 0; nt < 4; nt++) mma_f16(acc[mt][nt], a4, bh[nt]);
                ldsm4(a4, stb + (uint32_t)(1 * TILE_B + mloc * 80 + ka_ * 2));
#pragma unroll
                for (int nt = 0; nt < 4; nt++) mma_f16(acc[mt][nt], a4, bh[nt]);
            }
        }
    }

    // ---- epilogue: register-direct ----
    float* outF = Cf;
    __half* Chp = Chi;
    __half* Clp = Clo;
    int Nout = N;
    int nbase = bn;
    const float* bb = bias;
    if (mode == 3) {
        int part = bn / 768;
        Chp = Chi + (size_t)part * M * 768;
        Clp = Clo + (size_t)part * M * 768;
        nbase = bn - part * 768;
        Nout = 768;
        bb = (part == 0) ? bias : (part == 1) ? bias2 : bias3;
    } else if (mode == 4) {
        outF = Cf + (size_t)blockIdx.z * M * N;
    }

    const int r0 = lane >> 2, c0 = (lane & 3) * 2;
    float bv[4][2];
#pragma unroll
    for (int nt = 0; nt < 4; nt++) {
        int n = nbase + wn + nt * 8 + c0;
        bv[nt][0] = bb ? __ldg(bb + n) : 0.f;
        bv[nt][1] = bb ? __ldg(bb + n + 1) : 0.f;
    }

#pragma unroll
    for (int mt = 0; mt < 4; mt++) {
#pragma unroll
        for (int half_ = 0; half_ < 2; half_++) {
            int m = bm + wm + mt * 16 + half_ * 8 + r0;
            if (m >= M) continue;
#pragma unroll
            for (int nt = 0; nt < 4; nt++) {
                int n = nbase + wn + nt * 8 + c0;
                float v0 = acc[mt][nt][half_ * 2 + 0] + bv[nt][0];
                float v1 = acc[mt][nt][half_ * 2 + 1] + bv[nt][1];
                if (mode == 1 || mode == 3) {
                    if (mode == 1) {
                        v0 = 0.5f * v0 * (1.f + erff(v0 * 0.70710678118654752440f));
                        v1 = 0.5f * v1 * (1.f + erff(v1 * 0.70710678118654752440f));
                    }
                    uint32_t lo;
                    uint32_t hi = pack_split(v0, v1, lo);
                    *(uint32_t*)(Chp + (size_t)m * Nout + n) = hi;
                    *(uint32_t*)(Clp + (size_t)m * Nout + n) = lo;
                } else {
                    if (mode == 2) {
                        float2 rr = *(const float2*)(res + (size_t)m * N + n);
                        v0 += rr.x; v1 += rr.y;
                    }
                    float2 o; o.x = v0; o.y = v1;
                    *(float2*)(outF + (size_t)m * Nout + n) = o;
                }
            }
        }
    }
}

// ---------------- MMA attention (flash-style, 3-pass QK + 3-pass PV) ----------------
// 2 CTAs per (b,h): qbase 0 / 128. 8 warps, warp = 16 query rows.
// smem: Qh/Ql [128][72] resident; K/V blocks of 64 keys double-buffered.
#define APITCH 72                        // halves per row (144B), ldsm conflict-free
#define AQ_B   (128 * APITCH * 2)        // 18432 per Q array
#define AKV_B  (64 * APITCH * 2)         // 9216 per K/V array
#define AKV_ST (4 * AKV_B)               // 36864 per stage (Kh,Kl,Vh,Vl)
#define ASM_KV (2 * AQ_B)                // 36864
#define ASMEM  (ASM_KV + 2 * AKV_ST)     // 110592

__global__ __launch_bounds__(256, 2) void attn_mma(
    const __half* __restrict__ QKVh, const __half* __restrict__ QKVl,
    __half* __restrict__ Oh, __half* __restrict__ Ol)
{
    extern __shared__ __align__(128) char smem[];
    const uint32_t sb = smem_u32(smem);
    const int tid = threadIdx.x, wid = tid >> 5, lane = tid & 31;
    const int bh = blockIdx.x >> 1;
    const int b = bh / NH, h = bh % NH;
    const int qbase = (blockIdx.x & 1) * 128;
    const size_t tokb = (size_t)b * SEQ;
    const int hoff = h * DH;

    // ---- issue Q stage (group 0): Qh, Ql 128 rows x 64 halves ----
#pragma unroll
    for (int j = 0; j < 8; j++) {
        int idx = tid + j * 256;             // 2048 chunks
        int arr = idx >> 10, c = idx & 1023;
        int row = c >> 3, chk = c & 7;
        int q = min(qbase + row, SEQ - 1);
        const __half* srcb = arr ? QKVl : QKVh;     // part 0 = Q
        cp16(sb + (uint32_t)(arr * AQ_B + row * 144 + chk * 16),
             srcb + (tokb + q) * BD + hoff + chk * 8);
    }
    CP_COMMIT();

    auto load_kv = [&](int kb) {
        uint32_t stb = sb + ASM_KV + (uint32_t)(kb & 1) * AKV_ST;
#pragma unroll
        for (int j = 0; j < 8; j++) {
            int idx = tid + j * 256;         // 2048: arr(4) x row(64) x chk(8)
            int arr = idx >> 9, c = idx & 511;
            int row = c >> 3, chk = c & 7;
            int key = min(kb * 64 + row, SEQ - 1);
            const __half* srcb = (arr & 1) ? QKVl : QKVh;
            int part = 1 + (arr >> 1);       // K = part1, V = part2
            cp16(stb + (uint32_t)(arr * AKV_B + row * 144 + chk * 16),
                 srcb + ((size_t)part * NTOK + tokb + key) * BD + hoff + chk * 8);
        }
        CP_COMMIT();
    };

    load_kv(0);
    load_kv(1);
    CP_WAIT2();            // Q arrived
    __syncthreads();

    const int g = lane >> 3, r = lane & 7;
    const int mrowA = wid * 16 + (g & 1) * 8 + r;   // A-frag row base (Q and P share)

    float o[8][4];
#pragma unroll
    for (int dt = 0; dt < 8; dt++)
#pragma unroll
        for (int e = 0; e < 4; e++) o[dt][e] = 0.f;
    float m0 = -1e30f, m1 = -1e30f, l0 = 0.f, l1 = 0.f;

    for (int kb = 0; kb < 4; kb++) {
        if (kb < 3) CP_WAIT1(); else CP_WAIT0();
        __syncthreads();
        const uint32_t stb = sb + ASM_KV + (uint32_t)(kb & 1) * AKV_ST;

        // ---- S = Q K^T (3-pass split) ----
        float s[8][4];
#pragma unroll
        for (int nt = 0; nt < 8; nt++)
#pragma unroll
            for (int e = 0; e < 4; e++) s[nt][e] = 0.f;

#pragma unroll
        for (int k16 = 0; k16 < 4; k16++) {
            uint32_t a4h[4], a4l[4];
            int ka = k16 * 16 + (g >> 1) * 8;
            ldsm4(a4h, sb + (uint32_t)(0 * AQ_B + mrowA * 144 + ka * 2));
            ldsm4(a4l, sb + (uint32_t)(1 * AQ_B + mrowA * 144 + ka * 2));
            int kb_ = k16 * 16 + (g & 1) * 8;
#pragma unroll
            for (int nt2 = 0; nt2 < 4; nt2++) {
                int nloc = nt2 * 16 + (g >> 1) * 8 + r;
                uint32_t b4h[4], b4l[4];
                ldsm4(b4h, stb + (uint32_t)(0 * AKV_B + nloc * 144 + kb_ * 2));
                ldsm4(b4l, stb + (uint32_t)(1 * AKV_B + nloc * 144 + kb_ * 2));
                mma_f16(s[nt2 * 2 + 0], a4h, &b4h[0]);
                mma_f16(s[nt2 * 2 + 0], a4l, &b4h[0]);
                mma_f16(s[nt2 * 2 + 0], a4h, &b4l[0]);
                mma_f16(s[nt2 * 2 + 1], a4h, &b4h[2]);
                mma_f16(s[nt2 * 2 + 1], a4l, &b4h[2]);
                mma_f16(s[nt2 * 2 + 1], a4h, &b4l[2]);
            }
        }

        // ---- scale + mask + online softmax ----
        float mx0 = -1e30f, mx1 = -1e30f;
#pragma unroll
        for (int nt = 0; nt < 8; nt++) {
            int gk = kb * 64 + nt * 8 + (lane & 3) * 2;
            s[nt][0] = (gk     < SEQ) ? s[nt][0] * 0.125f : -1e30f;
            s[nt][1] = (gk + 1 < SEQ) ? s[nt][1] * 0.125f : -1e30f;
            s[nt][2] = (gk     < SEQ) ? s[nt][2] * 0.125f : -1e30f;
            s[nt][3] = (gk + 1 < SEQ) ? s[nt][3] * 0.125f : -1e30f;
            mx0 = fmaxf(mx0, fmaxf(s[nt][0], s[nt][1]));
            mx1 = fmaxf(mx1, fmaxf(s[nt][2], s[nt][3]));
        }
        mx0 = fmaxf(mx0, __shfl_xor_sync(0xffffffffu, mx0, 1));
        mx0 = fmaxf(mx0, __shfl_xor_sync(0xffffffffu, mx0, 2));
        mx1 = fmaxf(mx1, __shfl_xor_sync(0xffffffffu, mx1, 1));
        mx1 = fmaxf(mx1, __shfl_xor_sync(0xffffffffu, mx1, 2));

        float m0n = fmaxf(m0, mx0), m1n = fmaxf(m1, mx1);
        float a0 = __expf(m0 - m0n), a1 = __expf(m1 - m1n);
        float sum0 = 0.f, sum1 = 0.f;
#pragma unroll
        for (int nt = 0; nt < 8; nt++) {
            float p0 = __expf(s[nt][0] - m0n);
            float p1 = __expf(s[nt][1] - m0n);
            float p2 = __expf(s[nt][2] - m1n);
            float p3 = __expf(s[nt][3] - m1n);
            s[nt][0] = p0; s[nt][1] = p1; s[nt][2] = p2; s[nt][3] = p3;
            sum0 += p0 + p1;
            sum1 += p2 + p3;
        }
        sum0 += __shfl_xor_sync(0xffffffffu, sum0, 1);
        sum0 += __shfl_xor_sync(0xffffffffu, sum0, 2);
        sum1 += __shfl_xor_sync(0xffffffffu, sum1, 1);
        sum1 += __shfl_xor_sync(0xffffffffu, sum1, 2);
        l0 = l0 * a0 + sum0;
        l1 = l1 * a1 + sum1;
        m0 = m0n; m1 = m1n;
#pragma unroll
        for (int dt = 0; dt < 8; dt++) {
            o[dt][0] *= a0; o[dt][1] *= a0;
            o[dt][2] *= a1; o[dt][3] *= a1;
        }

        // ---- O += P V (3-pass split; P A-frags direct from S regs) ----
#pragma unroll
        for (int k16 = 0; k16 < 4; k16++) {
            uint32_t ph[4], pl[4];
            ph[0] = pack_split(s[2 * k16][0],     s[2 * k16][1],     pl[0]);
            ph[1] = pack_split(s[2 * k16][2],     s[2 * k16][3],     pl[1]);
            ph[2] = pack_split(s[2 * k16 + 1][0], s[2 * k16 + 1][1], pl[2]);
            ph[3] = pack_split(s[2 * k16 + 1][2], s[2 * k16 + 1][3], pl[3]);
            int krow = k16 * 16 + (g & 1) * 8 + r;
#pragma unroll
            for (int dt2 = 0; dt2 < 4; dt2++) {
                int doff = dt2 * 16 + (g >> 1) * 8;
                uint32_t b4h[4], b4l[4];
                ldsm4t(b4h, stb + (uint32_t)(2 * AKV_B + krow * 144 + doff * 2));
                ldsm4t(b4l, stb + (uint32_t)(3 * AKV_B + krow * 144 + doff * 2));
                mma_f16(o[dt2 * 2 + 0], ph, &b4h[0]);
                mma_f16(o[dt2 * 2 + 0], pl, &b4h[0]);
                mma_f16(o[dt2 * 2 + 0], ph, &b4l[0]);
                mma_f16(o[dt2 * 2 + 1], ph, &b4h[2]);
                mma_f16(o[dt2 * 2 + 1], pl, &b4h[2]);
                mma_f16(o[dt2 * 2 + 1], ph, &b4l[2]);
            }
        }

        __syncthreads();
        if (kb + 2 < 4) load_kv(kb + 2);
    }

    // ---- normalize + split-fp16 store ----
    float inv0 = 1.f / l0, inv1 = 1.f / l1;
    int q0 = qbase + wid * 16 + (lane >> 2);
    int q1 = q0 + 8;
#pragma unroll
    for (int dt = 0; dt < 8; dt++) {
        int col = hoff + dt * 8 + (lane & 3) * 2;
        if (q0 < SEQ) {
            uint32_t lo;
            uint32_t hi = pack_split(o[dt][0] * inv0, o[dt][1] * inv0, lo);
            *(uint32_t*)(Oh + (tokb + q0) * BD + col) = hi;
            *(uint32_t*)(Ol + (tokb + q0) * BD + col) = lo;
        }
        if (q1 < SEQ) {
            uint32_t lo;
            uint32_t hi = pack_split(o[dt][2] * inv1, o[dt][3] * inv1, lo);
            *(uint32_t*)(Oh + (tokb + q1) * BD + col) = hi;
            *(uint32_t*)(Ol + (tokb + q1) * BD + col) = lo;
        }
    }
}

// ---------------- split-K combine (plain, last layer) ----------------
__global__ void combine_k(float* __restrict__ x, const float* __restrict__ p0,
                          const float* __restrict__ p1, const float* __restrict__ bias)
{
    int i = blockIdx.x * blockDim.x + threadIdx.x;
    if (i < NTOK * BD) {
        x[i] += p0[i] + p1[i] + bias[i % BD];
    }
}

// ---------------- weight prep: transpose W[K,N] fp32 -> fp16 [N,K], one launch ----------------
__device__ __forceinline__ void wsplit_tile(
    const float* __restrict__ s, __half* __restrict__ oh,
    int K, int N, int kb, int nb, float (*t)[33])
{
    const int tx = threadIdx.x & 31, ty = threadIdx.x >> 5;
#pragma unroll
    for (int r = 0; r < 4; r++) {
        int row = ty + (r << 3);
        t[row][tx] = s[(size_t)(kb + row) * N + nb + tx];
    }
    __syncthreads();
#pragma unroll
    for (int r = 0; r < 4; r++) {
        int row = ty + (r << 3);
        oh[(size_t)(nb + row) * K + kb + tx] = __float2half_rn(t[tx][row]);
    }
}

#define WPREP_PER_L 6912    // 4*576 + 2*2304
#define WPREP_BLOCKS (NLAY * WPREP_PER_L + 576)

__global__ __launch_bounds__(256) void wprep_all(
    const float* __restrict__ Wq, const float* __restrict__ Wk,
    const float* __restrict__ Wv, const float* __restrict__ Wo,
    const float* __restrict__ Wf1, const float* __restrict__ Wf2,
    const float* __restrict__ pw,
    __half* __restrict__ wh, __half* __restrict__ pwh)
{
    __shared__ float t[32][33];
    int bid = blockIdx.x;
    if (bid >= NLAY * WPREP_PER_L) {
        int idx = bid - NLAY * WPREP_PER_L;
#pragma unroll
        for (int r = 0; r < 4; r++) {
            int i = idx * 1024 + r * 256 + threadIdx.x;
            pwh[i] = __float2half_rn(pw[i]);
        }
        return;
    }
    int l = bid / WPREP_PER_L, r = bid % WPREP_PER_L;
    const float* src; size_t doff; int K, N, idx;
    if (r < 2304) {
        int g = r / 576; idx = r % 576;
        src = (g == 0 ? Wq : g == 1 ? Wk : g == 2 ? Wv : Wo) + (size_t)l * SZ_D2;
        doff = (size_t)g * SZ_D2; K = 768; N = 768;
    } else if (r < 4608) {
        idx = r - 2304; src = Wf1 + (size_t)l * SZ_DF; doff = OFF_F1; K = 768; N = 3072;
    } else {
        idx = r - 4608; src = Wf2 + (size_t)l * SZ_DF; doff = OFF_F2; K = 3072; N = 768;
    }
    int ntx = N / 32;
    int tx = idx % ntx, ty = idx / ntx;
    wsplit_tile(src, wh + (size_t)l * LW + doff, K, N, ty * 32, tx * 32, t);
}

// ---------------- layernorm ----------------
__device__ __forceinline__ float block_sum(float v, float* red)
{
#pragma unroll
    for (int o = 16; o; o >>= 1) v += __shfl_xor_sync(0xffffffffu, v, o);
    int w = threadIdx.x >> 5;
    if ((threadIdx.x & 31) == 0) red[w] = v;
    __syncthreads();
    float t = 0.f;
    if (threadIdx.x < 32) {
        t = (threadIdx.x < 8) ? red[threadIdx.x] : 0.f;
#pragma unroll
        for (int o = 4; o; o >>= 1) t += __shfl_xor_sync(0xffffffffu, t, o);
        if (threadIdx.x == 0) red[0] = t;
    }
    __syncthreads();
    float r = red[0];
    __syncthreads();
    return r;
}

__global__ __launch_bounds__(256) void ln_kernel(
    const float* __restrict__ X, const float* __restrict__ g,
    const float* __restrict__ bb, float* __restrict__ out, size_t in_stride)
{
    __shared__ float red[8];
    const int tid = threadIdx.x;
    const float* xr = X + (size_t)blockIdx.x * in_stride;
    float v0 = xr[tid], v1 = xr[tid + 256], v2 = xr[tid + 512];
    float s = block_sum(v0 + v1 + v2, red);
    float mean = s * (1.f / 768.f);
    float d0 = v0 - mean, d1 = v1 - mean, d2 = v2 - mean;
    float sq = block_sum(d0 * d0 + d1 * d1 + d2 * d2, red);
    float rstd = rsqrtf(sq * (1.f / 768.f) + 1e-5f);
    float* orow = out + (size_t)blockIdx.x * BD;
    orow[tid]       = d0 * rstd * g[tid]       + bb[tid];
    orow[tid + 256] = d1 * rstd * g[tid + 256] + bb[tid + 256];
    orow[tid + 512] = d2 * rstd * g[tid + 512] + bb[tid + 512];
}

__device__ __forceinline__ void ln_core_split(
    float v0, float v1, float v2, const float* g, const float* bb,
    __half* oh, __half* ol, size_t ro, int tid, float* red)
{
    float s = block_sum(v0 + v1 + v2, red);
    float mean = s * (1.f / 768.f);
    float d0 = v0 - mean, d1 = v1 - mean, d2 = v2 - mean;
    float sq = block_sum(d0 * d0 + d1 * d1 + d2 * d2, red);
    float rstd = rsqrtf(sq * (1.f / 768.f) + 1e-5f);
#pragma unroll
    for (int j = 0; j < 3; j++) {
        float d = (j == 0) ? d0 : (j == 1) ? d1 : d2;
        int c = tid + j * 256;
        float y = d * rstd * g[c] + bb[c];
        __half h, l;
        split_h(y, h, l);
        oh[ro + c] = h;
        ol[ro + c] = l;
    }
}

__global__ __launch_bounds__(256) void ln_split(
    const float* __restrict__ X, const float* __restrict__ g,
    const float* __restrict__ bb, __half* __restrict__ oh, __half* __restrict__ ol)
{
    __shared__ float red[8];
    const int tid = threadIdx.x;
    size_t ro = (size_t)blockIdx.x * BD;
    float v0 = X[ro + tid], v1 = X[ro + tid + 256], v2 = X[ro + tid + 512];
    ln_core_split(v0, v1, v2, g, bb, oh, ol, ro, tid, red);
}

// fused: x += p0 + p1 + bias_ff2; then LN(x) -> split fp16
__global__ __launch_bounds__(256) void combine_ln_split(
    float* __restrict__ x, const float* __restrict__ p0, const float* __restrict__ p1,
    const float* __restrict__ bf2v, const float* __restrict__ g,
    const float* __restrict__ bb, __half* __restrict__ oh, __half* __restrict__ ol)
{
    __shared__ float red[8];
    const int tid = threadIdx.x;
    size_t ro = (size_t)blockIdx.x * BD;
    float v0 = x[ro + tid]       + p0[ro + tid]       + p1[ro + tid]       + bf2v[tid];
    float v1 = x[ro + tid + 256] + p0[ro + tid + 256] + p1[ro + tid + 256] + bf2v[tid + 256];
    float v2 = x[ro + tid + 512] + p0[ro + tid + 512] + p1[ro + tid + 512] + bf2v[tid + 512];
    x[ro + tid] = v0; x[ro + tid + 256] = v1; x[ro + tid + 512] = v2;
    ln_core_split(v0, v1, v2, g, bb, oh, ol, ro, tid, red);
}

// ---------------- small kernels ----------------
__global__ void im2col_split(const float* __restrict__ X, __half* __restrict__ ch,
                             __half* __restrict__ cl)
{
    int idx = blockIdx.x * blockDim.x + threadIdx.x;
    if (idx >= NPATCH * BD) return;
    int m = idx / BD, kk = idx - m * BD;
    int b = m / 196, hw = m - b * 196;
    int ph = hw / 14, pw = hw - ph * 14;
    int c = kk >> 8, r = kk & 255, p = r >> 4, q = r & 15;
    float v = X[((size_t)(b * 3 + c) * 224 + ph * 16 + p) * 224 + pw * 16 + q];
    __half h, l;
    split_h(v, h, l);
    ch[idx] = h;
    cl[idx] = l;
}

__global__ void assemble_k(const float* __restrict__ patches, const float* __restrict__ cls,
                           const float* __restrict__ pos, float* __restrict__ x)
{
    int idx = blockIdx.x * blockDim.x + threadIdx.x;
    if (idx >= NTOK * BD) return;
    int d = idx % BD;
    int t = idx / BD;
    int b = t / SEQ, s = t - b * SEQ;
    float v = (s == 0) ? cls[d] : patches[((size_t)b * 196 + (s - 1)) * BD + d];
    x[idx] = v + pos[(size_t)s * BD + d];
}

__global__ __launch_bounds__(256) void head_kernel(
    const float* __restrict__ xc, const float* __restrict__ W,
    const float* __restrict__ bias, float* __restrict__ out)
{
    __shared__ float xs[BD];
    const int b = blockIdx.x;
    for (int i = threadIdx.x; i < BD; i += 256) xs[i] = xc[(size_t)b * BD + i];
    __syncthreads();

    const int n0 = threadIdx.x;
    float acc[4] = {0.f, 0.f, 0.f, 0.f};
    for (int k = 0; k < BD; k++) {
        float xv = xs[k];
#pragma unroll
        for (int j = 0; j < 4; j++) {
            int n = n0 + j * 256;
            if (n < NCLS) acc[j] += xv * W[(size_t)k * NCLS + n];
        }
    }
#pragma unroll
    for (int j = 0; j < 4; j++) {
        int n = n0 + j * 256;
        if (n < NCLS) out[(size_t)b * NCLS + n] = acc[j] + bias[n];
    }
}

// ---------------- launch ----------------
extern "C" void kernel_launch(void* const* d_in, const int* in_sizes, int n_in,
                              void* d_out, int out_size)
{
    const float* X       = (const float*)d_in[0];
    const float* patch_w = (const float*)d_in[1];
    const float* patch_b = (const float*)d_in[2];
    const float* cls_tok = (const float*)d_in[3];
    const float* pos_emb = (const float*)d_in[4];
    const float* ln1_g   = (const float*)d_in[5];
    const float* ln1_b   = (const float*)d_in[6];
    const float* Wq      = (const float*)d_in[7];
    const float* bq      = (const float*)d_in[8];
    const float* Wk      = (const float*)d_in[9];
    const float* bk      = (const float*)d_in[10];
    const float* Wv      = (const float*)d_in[11];
    const float* bv      = (const float*)d_in[12];
    const float* Wo      = (const float*)d_in[13];
    const float* bo      = (const float*)d_in[14];
    const float* ln2_g   = (const float*)d_in[15];
    const float* ln2_b   = (const float*)d_in[16];
    const float* Wf1     = (const float*)d_in[17];
    const float* bf1     = (const float*)d_in[18];
    const float* Wf2     = (const float*)d_in[19];
    const float* bf2     = (const float*)d_in[20];
    const float* lnf_g   = (const float*)d_in[21];
    const float* lnf_b   = (const float*)d_in[22];
    const float* head_w  = (const float*)d_in[23];
    const float* head_b  = (const float*)d_in[24];
    float* out = (float*)d_out;

    float *x, *h, *pp, *cls;
    __half *qkvh, *qkvl, *hh, *hl, *ah, *al, *fh, *fl, *ch, *cl, *wh, *pwh;
    cudaGetSymbolAddress((void**)&x,    g_x);
    cudaGetSymbolAddress((void**)&h,    g_h);
    cudaGetSymbolAddress((void**)&pp,   g_pp);
    cudaGetSymbolAddress((void**)&cls,  g_cls);
    cudaGetSymbolAddress((void**)&qkvh, g_qkvh);
    cudaGetSymbolAddress((void**)&qkvl, g_qkvl);
    cudaGetSymbolAddress((void**)&hh,   g_hh);
    cudaGetSymbolAddress((void**)&hl,   g_hl);
    cudaGetSymbolAddress((void**)&ah,   g_ah);
    cudaGetSymbolAddress((void**)&al,   g_al);
    cudaGetSymbolAddress((void**)&fh,   g_fh);
    cudaGetSymbolAddress((void**)&fl,   g_fl);
    cudaGetSymbolAddress((void**)&ch,   g_ch);
    cudaGetSymbolAddress((void**)&cl,   g_cl);
    cudaGetSymbolAddress((void**)&wh,   g_wh);
    cudaGetSymbolAddress((void**)&pwh,  g_pwh);

    cudaFuncSetAttribute(gemm_tc, cudaFuncAttributeMaxDynamicSharedMemorySize, GT_SMEM);
    cudaFuncSetAttribute(attn_mma, cudaFuncAttributeMaxDynamicSharedMemorySize, ASMEM);

    // weight prep: one launch
    wprep_all<<<WPREP_BLOCKS, 256>>>(Wq, Wk, Wv, Wo, Wf1, Wf2, patch_w, wh, pwh);

    // patch embed
    im2col_split<<<(NPATCH * BD + 255) / 256, 256>>>(X, ch, cl);
    gemm_tc<<<dim3(6, 49), 256, GT_SMEM>>>(ch, cl, pwh, patch_b, nullptr, nullptr, nullptr,
                                           h, nullptr, nullptr, NPATCH, BD, BD, BD, 0);
    assemble_k<<<(NTOK * BD + 255) / 256, 256>>>(h, cls_tok, pos_emb, x);

    const dim3 gQKV(18, 50);       // N=2304 merged, split-fp16 epilogue
    const dim3 gD(6, 50);          // N=768
    const dim3 gF1(24, 50);        // N=3072
    const dim3 gF2(6, 50, 2);      // N=768, split-K=2

    float* p0F = pp;
    float* p1F = pp + (size_t)NTOK * BD;

    for (int l = 0; l < NLAY; l++) {
        const __half* wlh = wh + (size_t)l * LW;

        if (l == 0)
            ln_split<<<NTOK, 256>>>(x, ln1_g, ln1_b, hh, hl);
        else
            combine_ln_split<<<NTOK, 256>>>(x, p0F, p1F, bf2 + (l - 1) * BD,
                                            ln1_g + l * BD, ln1_b + l * BD, hh, hl);

        gemm_tc<<<gQKV, 256, GT_SMEM>>>(hh, hl, wlh + OFF_Q,
                                        bq + l * BD, bk + l * BD, bv + l * BD, nullptr,
                                        nullptr, qkvh, qkvl, NTOK, 3 * BD, BD, BD, 3);

        attn_mma<<<BATCH * NH * 2, 256, ASMEM>>>(qkvh, qkvl, ah, al);

        gemm_tc<<<gD, 256, GT_SMEM>>>(ah, al, wlh + OFF_O,
                                      bo + l * BD, nullptr, nullptr, x,
                                      x, nullptr, nullptr, NTOK, BD, BD, BD, 2);

        ln_split<<<NTOK, 256>>>(x, ln2_g + l * BD, ln2_b + l * BD, hh, hl);

        gemm_tc<<<gF1, 256, GT_SMEM>>>(hh, hl, wlh + OFF_F1,
                                       bf1 + l * FF, nullptr, nullptr, nullptr,
                                       nullptr, fh, fl, NTOK, FF, BD, BD, 1);

        gemm_tc<<<gF2, 256, GT_SMEM>>>(fh, fl, wlh + OFF_F2,
                                       nullptr, nullptr, nullptr, nullptr,
                                       pp, nullptr, nullptr, NTOK, BD, FF / 2, FF, 4);
    }

    combine_k<<<(NTOK * BD + 255) / 256, 256>>>(x, p0F, p1F, bf2 + 11 * BD);
    ln_kernel<<<BATCH, 256>>>(x, lnf_g, lnf_b, cls, (size_t)SEQ * BD);
    head_kernel<<<BATCH, 256>>>(cls, head_w, head_b, out);
}